// round 1
// baseline (speedup 1.0000x reference)
#include <cuda_runtime.h>
#include <math.h>

#define B_ 4096
#define D_ 128
#define K_ 4096
#define E_ 1024
#define H_ 2048
#define V_ 64

// ---------------- scratch (static device globals; no allocation) ----------------
__device__ float g_s[(size_t)B_ * K_];   // diff -> score p -> logits -> att p (64 MB)
__device__ float g_e[(size_t)B_ * E_];   // 16 MB
__device__ float g_h[(size_t)B_ * H_];   // 32 MB
__device__ float g_x2[B_];
__device__ float g_k2[K_];
__device__ float g_rsc[B_];              // per-row 1/sum (score, then att)

// ---------------- squared row norms (one warp per row, D=128) ----------------
__global__ void sqnorm_kernel(const float* __restrict__ m, float* __restrict__ out, int rows) {
    int warp = (blockIdx.x * blockDim.x + threadIdx.x) >> 5;
    int lane = threadIdx.x & 31;
    if (warp >= rows) return;
    const float* r = m + (size_t)warp * D_;
    float s = 0.f;
    #pragma unroll
    for (int i = lane; i < D_; i += 32) { float v = r[i]; s += v * v; }
    #pragma unroll
    for (int o = 16; o; o >>= 1) s += __shfl_xor_sync(0xffffffffu, s, o);
    if (lane == 0) out[warp] = s;
}

// ---------------- generic tiled SGEMM with fused epilogues ----------------
// A: [M,Kd] row-major.  B (TRB=0): [Kd,N] row-major.  B (TRB=1): [N,Kd] row-major.
enum { EPI_DIST = 1, EPI_RELU_BIAS = 2, EPI_BIAS = 3, EPI_SRELU_BIAS = 4, EPI_SCALE = 5 };

template<int BM, int BN, int BK, int TM, int TN, bool TRB, int EPI>
__global__ void __launch_bounds__((BM / TM) * (BN / TN))
sgemm(const float* __restrict__ A, const float* __restrict__ Bm,
      float* __restrict__ C, int M, int N, int Kd,
      const float* __restrict__ aux0,   // x2 (DIST) or row-scale (SRELU/SCALE)
      const float* __restrict__ aux1,   // k2 (DIST)
      const float* __restrict__ bias)
{
    constexpr int NT = (BM / TM) * (BN / TN);
    __shared__ float As[BK][BM + 4];
    __shared__ float Bs[BK][BN + 4];

    const int tid = threadIdx.x;
    const int rowBase = blockIdx.y * BM;
    const int colBase = blockIdx.x * BN;
    const int tx = tid % (BN / TN);
    const int ty = tid / (BN / TN);

    float acc[TM][TN];
    #pragma unroll
    for (int i = 0; i < TM; ++i)
        #pragma unroll
        for (int j = 0; j < TN; ++j) acc[i][j] = 0.f;

    for (int k0 = 0; k0 < Kd; k0 += BK) {
        // stage A tile (BM x BK), transposed into As[k][m]
        #pragma unroll
        for (int i = tid * 4; i < BM * BK; i += NT * 4) {
            int r = i / BK, c = i % BK;
            float4 v = *(const float4*)(A + (size_t)(rowBase + r) * Kd + k0 + c);
            As[c + 0][r] = v.x; As[c + 1][r] = v.y; As[c + 2][r] = v.z; As[c + 3][r] = v.w;
        }
        // stage B tile (BK x BN)
        if (!TRB) {
            #pragma unroll
            for (int i = tid * 4; i < BK * BN; i += NT * 4) {
                int r = i / BN, c = i % BN;
                float4 v = *(const float4*)(Bm + (size_t)(k0 + r) * N + colBase + c);
                *(float4*)&Bs[r][c] = v;
            }
        } else {
            #pragma unroll
            for (int i = tid * 4; i < BN * BK; i += NT * 4) {
                int n = i / BK, c = i % BK;
                float4 v = *(const float4*)(Bm + (size_t)(colBase + n) * Kd + k0 + c);
                Bs[c + 0][n] = v.x; Bs[c + 1][n] = v.y; Bs[c + 2][n] = v.z; Bs[c + 3][n] = v.w;
            }
        }
        __syncthreads();

        #pragma unroll
        for (int k = 0; k < BK; ++k) {
            float a[TM], b[TN];
            #pragma unroll
            for (int i = 0; i < TM; ++i) a[i] = As[k][ty * TM + i];
            #pragma unroll
            for (int j = 0; j < TN; ++j) b[j] = Bs[k][tx * TN + j];
            #pragma unroll
            for (int i = 0; i < TM; ++i)
                #pragma unroll
                for (int j = 0; j < TN; ++j)
                    acc[i][j] += a[i] * b[j];
        }
        __syncthreads();
    }

    // epilogue
    #pragma unroll
    for (int i = 0; i < TM; ++i) {
        const int row = rowBase + ty * TM + i;
        float r0 = 0.f;
        if (EPI == EPI_DIST || EPI == EPI_SRELU_BIAS || EPI == EPI_SCALE) r0 = aux0[row];
        #pragma unroll
        for (int j = 0; j < TN; ++j) {
            const int col = colBase + tx * TN + j;
            float v = acc[i][j];
            if (EPI == EPI_DIST) {
                float d2 = r0 + aux1[col] - 2.f * v;
                v = sqrtf(fmaxf(d2, 0.f));
            } else if (EPI == EPI_RELU_BIAS) {
                v = fmaxf(v + bias[col], 0.f);
            } else if (EPI == EPI_BIAS) {
                v = v + bias[col];
            } else if (EPI == EPI_SRELU_BIAS) {
                v = fmaxf(v * r0 + bias[col], 0.f);
            } else if (EPI == EPI_SCALE) {
                v = v * r0;
            }
            C[(size_t)row * N + col] = v;
        }
    }
}

// ---------------- score: p = exp(-10*diff/rowmax); store p and 1/sum ----------------
__global__ void __launch_bounds__(256) score_kernel(float* __restrict__ s, float* __restrict__ rsc) {
    const int row = blockIdx.x;
    float* p = s + (size_t)row * K_;
    const int tid = threadIdx.x;
    constexpr int PT = K_ / 256;
    float v[PT];
    float mx = 0.f;
    #pragma unroll
    for (int i = 0; i < PT; ++i) { v[i] = p[tid + i * 256]; mx = fmaxf(mx, v[i]); }
    __shared__ float red[256];
    red[tid] = mx; __syncthreads();
    #pragma unroll
    for (int o = 128; o; o >>= 1) { if (tid < o) red[tid] = fmaxf(red[tid], red[tid + o]); __syncthreads(); }
    mx = red[0];
    __syncthreads();
    const float scale = -10.f / mx;
    float sum = 0.f;
    #pragma unroll
    for (int i = 0; i < PT; ++i) { v[i] = __expf(v[i] * scale); sum += v[i]; }
    red[tid] = sum; __syncthreads();
    #pragma unroll
    for (int o = 128; o; o >>= 1) { if (tid < o) red[tid] += red[tid + o]; __syncthreads(); }
    #pragma unroll
    for (int i = 0; i < PT; ++i) p[tid + i * 256] = v[i];
    if (tid == 0) rsc[row] = 1.f / red[0];
}

// ---------------- softmax (logits): p = exp(l - rowmax); store p and 1/sum ----------------
__global__ void __launch_bounds__(256) softmax_kernel(float* __restrict__ s, float* __restrict__ rsc) {
    const int row = blockIdx.x;
    float* p = s + (size_t)row * K_;
    const int tid = threadIdx.x;
    constexpr int PT = K_ / 256;
    float v[PT];
    float mx = -3.402823466e38f;
    #pragma unroll
    for (int i = 0; i < PT; ++i) { v[i] = p[tid + i * 256]; mx = fmaxf(mx, v[i]); }
    __shared__ float red[256];
    red[tid] = mx; __syncthreads();
    #pragma unroll
    for (int o = 128; o; o >>= 1) { if (tid < o) red[tid] = fmaxf(red[tid], red[tid + o]); __syncthreads(); }
    mx = red[0];
    __syncthreads();
    float sum = 0.f;
    #pragma unroll
    for (int i = 0; i < PT; ++i) { v[i] = __expf(v[i] - mx); sum += v[i]; }
    red[tid] = sum; __syncthreads();
    #pragma unroll
    for (int o = 128; o; o >>= 1) { if (tid < o) red[tid] += red[tid + o]; __syncthreads(); }
    #pragma unroll
    for (int i = 0; i < PT; ++i) p[tid + i * 256] = v[i];
    if (tid == 0) rsc[row] = 1.f / red[0];
}

// ---------------- launch ----------------
extern "C" void kernel_launch(void* const* d_in, const int* in_sizes, int n_in,
                              void* d_out, int out_size) {
    const float* x        = (const float*)d_in[0];
    const float* keys     = (const float*)d_in[1];
    const float* values   = (const float*)d_in[2];
    const float* W_embed  = (const float*)d_in[3];
    const float* b_embed  = (const float*)d_in[4];
    const float* W_hidden = (const float*)d_in[5];
    const float* b_hidden = (const float*)d_in[6];
    const float* W_att    = (const float*)d_in[7];
    const float* b_att    = (const float*)d_in[8];
    float* out = (float*)d_out;

    float *s, *e, *h, *x2, *k2, *rsc;
    cudaGetSymbolAddress((void**)&s,   g_s);
    cudaGetSymbolAddress((void**)&e,   g_e);
    cudaGetSymbolAddress((void**)&h,   g_h);
    cudaGetSymbolAddress((void**)&x2,  g_x2);
    cudaGetSymbolAddress((void**)&k2,  g_k2);
    cudaGetSymbolAddress((void**)&rsc, g_rsc);

    // 0. squared norms
    sqnorm_kernel<<<B_ / 8, 256>>>(x, x2, B_);
    sqnorm_kernel<<<K_ / 8, 256>>>(keys, k2, K_);

    // 1. diff = sqrt(max(x2 + k2 - 2 x keys^T, 0))  -> g_s
    {
        dim3 grid(K_ / 128, B_ / 128);
        sgemm<128, 128, 8, 8, 8, true, EPI_DIST><<<grid, 256>>>(
            x, keys, s, B_, K_, D_, x2, k2, nullptr);
    }

    // 2. score p (unnormalized) + 1/sum
    score_kernel<<<B_, 256>>>(s, rsc);

    // 3. e = relu((p @ W_embed) * inv_sum + b_embed)
    {
        dim3 grid(E_ / 128, B_ / 128);
        sgemm<128, 128, 8, 8, 8, false, EPI_SRELU_BIAS><<<grid, 256>>>(
            s, W_embed, e, B_, E_, K_, rsc, nullptr, b_embed);
    }

    // 4. h = relu(e @ W_hidden + b_hidden)
    {
        dim3 grid(H_ / 128, B_ / 128);
        sgemm<128, 128, 8, 8, 8, false, EPI_RELU_BIAS><<<grid, 256>>>(
            e, W_hidden, h, B_, H_, E_, nullptr, nullptr, b_hidden);
    }

    // 5. logits = h @ W_att + b_att  -> g_s (reuse)
    {
        dim3 grid(K_ / 128, B_ / 128);
        sgemm<128, 128, 8, 8, 8, false, EPI_BIAS><<<grid, 256>>>(
            h, W_att, s, B_, K_, H_, nullptr, nullptr, b_att);
    }

    // 6. softmax p (unnormalized) + 1/sum
    softmax_kernel<<<B_, 256>>>(s, rsc);

    // 7. out = (p @ values) * inv_sum
    {
        dim3 grid(V_ / 64, B_ / 64);
        sgemm<64, 64, 16, 4, 4, false, EPI_SCALE><<<grid, 256>>>(
            s, values, out, B_, V_, K_, rsc, nullptr, nullptr);
    }
}

// round 4
// speedup vs baseline: 1.0545x; 1.0545x over previous
#include <cuda_runtime.h>
#include <cuda_bf16.h>
#include <stdint.h>
#include <math.h>

#define B_ 4096
#define D_ 128
#define K_ 4096
#define E_ 1024
#define H_ 2048
#define V_ 64

// ---------------- scratch (static device globals; no allocation) ----------------
__device__ float g_s[(size_t)B_ * K_];   // diff -> score p -> logits -> att p (64 MB)
__device__ float g_e[(size_t)B_ * E_];   // 16 MB
__device__ float g_h[(size_t)B_ * H_];   // 32 MB
__device__ float g_x2[B_];
__device__ float g_k2[K_];
__device__ float g_rsc[B_];              // per-row 1/sum (score, then att)

// ---------------- squared row norms (one warp per row, D=128) ----------------
__global__ void sqnorm_kernel(const float* __restrict__ m, float* __restrict__ out, int rows) {
    int warp = (blockIdx.x * blockDim.x + threadIdx.x) >> 5;
    int lane = threadIdx.x & 31;
    if (warp >= rows) return;
    const float* r = m + (size_t)warp * D_;
    float s = 0.f;
    #pragma unroll
    for (int i = lane; i < D_; i += 32) { float v = r[i]; s += v * v; }
    #pragma unroll
    for (int o = 16; o; o >>= 1) s += __shfl_xor_sync(0xffffffffu, s, o);
    if (lane == 0) out[warp] = s;
}

// ---------------- tensor-core GEMM (bf16 split hi/lo, 3-term) ----------------
// A: [M,Kd] row-major fp32.  B (TRB=0): [Kd,N] row-major.  B (TRB=1): [N,Kd] row-major.
enum { EPI_DIST = 1, EPI_RELU_BIAS = 2, EPI_BIAS = 3, EPI_SRELU_BIAS = 4, EPI_SCALE = 5 };

#define MMA_BF16(d, a, b)                                                      \
    asm volatile(                                                              \
        "mma.sync.aligned.m16n8k16.row.col.f32.bf16.bf16.f32 "                 \
        "{%0,%1,%2,%3}, {%4,%5,%6,%7}, {%8,%9}, {%0,%1,%2,%3};\n"              \
        : "+f"(d[0]), "+f"(d[1]), "+f"(d[2]), "+f"(d[3])                       \
        : "r"(a[0]), "r"(a[1]), "r"(a[2]), "r"(a[3]), "r"(b[0]), "r"(b[1]))

__device__ __forceinline__ void split_bf16(float v, __nv_bfloat16& h, __nv_bfloat16& l) {
    h = __float2bfloat16(v);
    l = __float2bfloat16(v - __bfloat162float(h));
}

template<int BM, int BN, int BK, int WM, int WN, bool TRB, int EPI>
__global__ void __launch_bounds__((BM / WM) * (BN / WN) * 32)
mma_gemm(const float* __restrict__ A, const float* __restrict__ Bm,
         float* __restrict__ C, int M, int N, int Kd,
         const float* __restrict__ aux0,   // x2 (DIST) or row-scale (SRELU/SCALE)
         const float* __restrict__ aux1,   // k2 (DIST)
         const float* __restrict__ bias)
{
    constexpr int WARPS_M = BM / WM, WARPS_N = BN / WN;
    constexpr int NT = WARPS_M * WARPS_N * 32;
    constexpr int LDT = BK + 8;            // bf16 elems per row; 20-word stride -> conflict-free frags
    constexpr int MF = WM / 16, NF = WN / 8;
    constexpr int ALD = BM * BK / (NT * 4);
    constexpr int BLD = BN * BK / (NT * 4);

    __shared__ __nv_bfloat16 As[2][BM * LDT];   // [hi|lo]
    __shared__ __nv_bfloat16 Bs[2][BN * LDT];   // stored n-major: Bs[n][k]

    const int tid = threadIdx.x;
    const int warp = tid >> 5, lane = tid & 31;
    const int wm = (warp / WARPS_N) * WM;
    const int wn = (warp % WARPS_N) * WN;
    const int rowBase = blockIdx.y * BM;
    const int colBase = blockIdx.x * BN;
    const int gq = lane >> 2, tq = lane & 3;

    float acc[MF][NF][4];
    #pragma unroll
    for (int i = 0; i < MF; ++i)
        #pragma unroll
        for (int j = 0; j < NF; ++j)
            #pragma unroll
            for (int c = 0; c < 4; ++c) acc[i][j][c] = 0.f;

    float4 areg[ALD], breg[BLD];

    // prologue: load k-chunk 0
    #pragma unroll
    for (int i = 0; i < ALD; ++i) {
        int idx = (tid + i * NT) * 4;
        int r = idx / BK, c = idx % BK;
        areg[i] = *(const float4*)(A + (size_t)(rowBase + r) * Kd + c);
    }
    #pragma unroll
    for (int i = 0; i < BLD; ++i) {
        int idx = (tid + i * NT) * 4;
        if (TRB) { int r = idx / BK, c = idx % BK;
                   breg[i] = *(const float4*)(Bm + (size_t)(colBase + r) * Kd + c); }
        else     { int r = idx / BN, c = idx % BN;
                   breg[i] = *(const float4*)(Bm + (size_t)r * N + colBase + c); }
    }

    for (int k0 = 0; k0 < Kd; k0 += BK) {
        // ---- stage regs -> smem with hi/lo conversion ----
        #pragma unroll
        for (int i = 0; i < ALD; ++i) {
            int idx = (tid + i * NT) * 4;
            int r = idx / BK, c = idx % BK;
            float4 v = areg[i];
            __nv_bfloat16 h0,h1,h2,h3,l0,l1,l2,l3;
            split_bf16(v.x,h0,l0); split_bf16(v.y,h1,l1);
            split_bf16(v.z,h2,l2); split_bf16(v.w,h3,l3);
            __nv_bfloat16* ph = &As[0][r * LDT + c];
            __nv_bfloat16* pl = &As[1][r * LDT + c];
            *(__nv_bfloat162*)(ph)     = __nv_bfloat162(h0, h1);
            *(__nv_bfloat162*)(ph + 2) = __nv_bfloat162(h2, h3);
            *(__nv_bfloat162*)(pl)     = __nv_bfloat162(l0, l1);
            *(__nv_bfloat162*)(pl + 2) = __nv_bfloat162(l2, l3);
        }
        #pragma unroll
        for (int i = 0; i < BLD; ++i) {
            int idx = (tid + i * NT) * 4;
            float4 v = breg[i];
            if (TRB) {
                int r = idx / BK, c = idx % BK;
                __nv_bfloat16 h0,h1,h2,h3,l0,l1,l2,l3;
                split_bf16(v.x,h0,l0); split_bf16(v.y,h1,l1);
                split_bf16(v.z,h2,l2); split_bf16(v.w,h3,l3);
                __nv_bfloat16* ph = &Bs[0][r * LDT + c];
                __nv_bfloat16* pl = &Bs[1][r * LDT + c];
                *(__nv_bfloat162*)(ph)     = __nv_bfloat162(h0, h1);
                *(__nv_bfloat162*)(ph + 2) = __nv_bfloat162(h2, h3);
                *(__nv_bfloat162*)(pl)     = __nv_bfloat162(l0, l1);
                *(__nv_bfloat162*)(pl + 2) = __nv_bfloat162(l2, l3);
            } else {
                int r = idx / BN, c = idx % BN;      // r = k, c = n
                float vv[4] = {v.x, v.y, v.z, v.w};
                #pragma unroll
                for (int j = 0; j < 4; ++j) {
                    __nv_bfloat16 h, l;
                    split_bf16(vv[j], h, l);
                    Bs[0][(c + j) * LDT + r] = h;
                    Bs[1][(c + j) * LDT + r] = l;
                }
            }
        }
        __syncthreads();

        // ---- prefetch next k-chunk into regs ----
        if (k0 + BK < Kd) {
            #pragma unroll
            for (int i = 0; i < ALD; ++i) {
                int idx = (tid + i * NT) * 4;
                int r = idx / BK, c = idx % BK;
                areg[i] = *(const float4*)(A + (size_t)(rowBase + r) * Kd + k0 + BK + c);
            }
            #pragma unroll
            for (int i = 0; i < BLD; ++i) {
                int idx = (tid + i * NT) * 4;
                if (TRB) { int r = idx / BK, c = idx % BK;
                           breg[i] = *(const float4*)(Bm + (size_t)(colBase + r) * Kd + k0 + BK + c); }
                else     { int r = idx / BN, c = idx % BN;
                           breg[i] = *(const float4*)(Bm + (size_t)(k0 + BK + r) * N + colBase + c); }
            }
        }

        // ---- compute ----
        #pragma unroll
        for (int ks = 0; ks < BK; ks += 16) {
            uint32_t ah[MF][4], al[MF][4], bh[NF][2], bl[NF][2];
            #pragma unroll
            for (int fm = 0; fm < MF; ++fm) {
                int row = wm + fm * 16 + gq;
                const __nv_bfloat16* p0 = &As[0][row * LDT + ks + tq * 2];
                const __nv_bfloat16* p1 = &As[0][(row + 8) * LDT + ks + tq * 2];
                ah[fm][0] = *(const uint32_t*)p0;
                ah[fm][1] = *(const uint32_t*)p1;
                ah[fm][2] = *(const uint32_t*)(p0 + 8);
                ah[fm][3] = *(const uint32_t*)(p1 + 8);
                const __nv_bfloat16* q0 = &As[1][row * LDT + ks + tq * 2];
                const __nv_bfloat16* q1 = &As[1][(row + 8) * LDT + ks + tq * 2];
                al[fm][0] = *(const uint32_t*)q0;
                al[fm][1] = *(const uint32_t*)q1;
                al[fm][2] = *(const uint32_t*)(q0 + 8);
                al[fm][3] = *(const uint32_t*)(q1 + 8);
            }
            #pragma unroll
            for (int fn = 0; fn < NF; ++fn) {
                int col = wn + fn * 8 + gq;
                const __nv_bfloat16* p = &Bs[0][col * LDT + ks + tq * 2];
                bh[fn][0] = *(const uint32_t*)p;
                bh[fn][1] = *(const uint32_t*)(p + 8);
                const __nv_bfloat16* q = &Bs[1][col * LDT + ks + tq * 2];
                bl[fn][0] = *(const uint32_t*)q;
                bl[fn][1] = *(const uint32_t*)(q + 8);
            }
            #pragma unroll
            for (int fm = 0; fm < MF; ++fm)
                #pragma unroll
                for (int fn = 0; fn < NF; ++fn) {
                    MMA_BF16(acc[fm][fn], ah[fm], bh[fn]);
                    MMA_BF16(acc[fm][fn], ah[fm], bl[fn]);
                    MMA_BF16(acc[fm][fn], al[fm], bh[fn]);
                }
        }
        __syncthreads();
    }

    // ---- epilogue ----
    #pragma unroll
    for (int fm = 0; fm < MF; ++fm) {
        #pragma unroll
        for (int half = 0; half < 2; ++half) {
            const int row = rowBase + wm + fm * 16 + gq + half * 8;
            float r0 = 0.f;
            if (EPI == EPI_DIST || EPI == EPI_SRELU_BIAS || EPI == EPI_SCALE) r0 = aux0[row];
            #pragma unroll
            for (int fn = 0; fn < NF; ++fn) {
                const int col = colBase + wn + fn * 8 + tq * 2;
                float v0 = acc[fm][fn][half * 2 + 0];
                float v1 = acc[fm][fn][half * 2 + 1];
                if (EPI == EPI_DIST) {
                    v0 = sqrtf(fmaxf(r0 + aux1[col]     - 2.f * v0, 0.f));
                    v1 = sqrtf(fmaxf(r0 + aux1[col + 1] - 2.f * v1, 0.f));
                } else if (EPI == EPI_RELU_BIAS) {
                    v0 = fmaxf(v0 + bias[col], 0.f);
                    v1 = fmaxf(v1 + bias[col + 1], 0.f);
                } else if (EPI == EPI_BIAS) {
                    v0 = v0 + bias[col];
                    v1 = v1 + bias[col + 1];
                } else if (EPI == EPI_SRELU_BIAS) {
                    v0 = fmaxf(v0 * r0 + bias[col], 0.f);
                    v1 = fmaxf(v1 * r0 + bias[col + 1], 0.f);
                } else if (EPI == EPI_SCALE) {
                    v0 *= r0; v1 *= r0;
                }
                float2 o; o.x = v0; o.y = v1;
                *(float2*)&C[(size_t)row * N + col] = o;
            }
        }
    }
}

// ---------------- score: p = exp(-10*diff/rowmax); store p and 1/sum ----------------
__global__ void __launch_bounds__(256) score_kernel(float* __restrict__ s, float* __restrict__ rsc) {
    const int row = blockIdx.x;
    float* p = s + (size_t)row * K_;
    const int tid = threadIdx.x;
    constexpr int PT = K_ / 256;
    float v[PT];
    float mx = 0.f;
    #pragma unroll
    for (int i = 0; i < PT; ++i) { v[i] = p[tid + i * 256]; mx = fmaxf(mx, v[i]); }
    __shared__ float red[256];
    red[tid] = mx; __syncthreads();
    #pragma unroll
    for (int o = 128; o; o >>= 1) { if (tid < o) red[tid] = fmaxf(red[tid], red[tid + o]); __syncthreads(); }
    mx = red[0];
    __syncthreads();
    const float scale = -10.f / mx;
    float sum = 0.f;
    #pragma unroll
    for (int i = 0; i < PT; ++i) { v[i] = __expf(v[i] * scale); sum += v[i]; }
    red[tid] = sum; __syncthreads();
    #pragma unroll
    for (int o = 128; o; o >>= 1) { if (tid < o) red[tid] += red[tid + o]; __syncthreads(); }
    #pragma unroll
    for (int i = 0; i < PT; ++i) p[tid + i * 256] = v[i];
    if (tid == 0) rsc[row] = 1.f / red[0];
}

// ---------------- softmax (logits): p = exp(l - rowmax); store p and 1/sum ----------------
__global__ void __launch_bounds__(256) softmax_kernel(float* __restrict__ s, float* __restrict__ rsc) {
    const int row = blockIdx.x;
    float* p = s + (size_t)row * K_;
    const int tid = threadIdx.x;
    constexpr int PT = K_ / 256;
    float v[PT];
    float mx = -3.402823466e38f;
    #pragma unroll
    for (int i = 0; i < PT; ++i) { v[i] = p[tid + i * 256]; mx = fmaxf(mx, v[i]); }
    __shared__ float red[256];
    red[tid] = mx; __syncthreads();
    #pragma unroll
    for (int o = 128; o; o >>= 1) { if (tid < o) red[tid] = fmaxf(red[tid], red[tid + o]); __syncthreads(); }
    mx = red[0];
    __syncthreads();
    float sum = 0.f;
    #pragma unroll
    for (int i = 0; i < PT; ++i) { v[i] = __expf(v[i] - mx); sum += v[i]; }
    red[tid] = sum; __syncthreads();
    #pragma unroll
    for (int o = 128; o; o >>= 1) { if (tid < o) red[tid] += red[tid + o]; __syncthreads(); }
    #pragma unroll
    for (int i = 0; i < PT; ++i) p[tid + i * 256] = v[i];
    if (tid == 0) rsc[row] = 1.f / red[0];
}

// ---------------- launch ----------------
extern "C" void kernel_launch(void* const* d_in, const int* in_sizes, int n_in,
                              void* d_out, int out_size) {
    const float* x        = (const float*)d_in[0];
    const float* keys     = (const float*)d_in[1];
    const float* values   = (const float*)d_in[2];
    const float* W_embed  = (const float*)d_in[3];
    const float* b_embed  = (const float*)d_in[4];
    const float* W_hidden = (const float*)d_in[5];
    const float* b_hidden = (const float*)d_in[6];
    const float* W_att    = (const float*)d_in[7];
    const float* b_att    = (const float*)d_in[8];
    float* out = (float*)d_out;

    float *s, *e, *h, *x2, *k2, *rsc;
    cudaGetSymbolAddress((void**)&s,   g_s);
    cudaGetSymbolAddress((void**)&e,   g_e);
    cudaGetSymbolAddress((void**)&h,   g_h);
    cudaGetSymbolAddress((void**)&x2,  g_x2);
    cudaGetSymbolAddress((void**)&k2,  g_k2);
    cudaGetSymbolAddress((void**)&rsc, g_rsc);

    // 0. squared norms
    sqnorm_kernel<<<B_ / 8, 256>>>(x, x2, B_);
    sqnorm_kernel<<<K_ / 8, 256>>>(keys, k2, K_);

    // 1. diff = sqrt(max(x2 + k2 - 2 x keys^T, 0))  -> g_s
    {
        dim3 grid(K_ / 128, B_ / 128);
        mma_gemm<128, 128, 32, 64, 32, true, EPI_DIST><<<grid, 256>>>(
            x, keys, s, B_, K_, D_, x2, k2, nullptr);
    }

    // 2. score p (unnormalized) + 1/sum
    score_kernel<<<B_, 256>>>(s, rsc);

    // 3. e = relu((p @ W_embed) * inv_sum + b_embed)
    {
        dim3 grid(E_ / 128, B_ / 128);
        mma_gemm<128, 128, 32, 64, 32, false, EPI_SRELU_BIAS><<<grid, 256>>>(
            s, W_embed, e, B_, E_, K_, rsc, nullptr, b_embed);
    }

    // 4. h = relu(e @ W_hidden + b_hidden)
    {
        dim3 grid(H_ / 128, B_ / 128);
        mma_gemm<128, 128, 32, 64, 32, false, EPI_RELU_BIAS><<<grid, 256>>>(
            e, W_hidden, h, B_, H_, E_, nullptr, nullptr, b_hidden);
    }

    // 5. logits = h @ W_att + b_att  -> g_s (reuse)
    {
        dim3 grid(K_ / 128, B_ / 128);
        mma_gemm<128, 128, 32, 64, 32, false, EPI_BIAS><<<grid, 256>>>(
            h, W_att, s, B_, K_, H_, nullptr, nullptr, b_att);
    }

    // 6. softmax p (unnormalized) + 1/sum
    softmax_kernel<<<B_, 256>>>(s, rsc);

    // 7. out = (p @ values) * inv_sum
    {
        dim3 grid(V_ / 64, B_ / 64);
        mma_gemm<64, 64, 32, 32, 32, false, EPI_SCALE><<<grid, 128>>>(
            s, values, out, B_, V_, K_, rsc, nullptr, nullptr);
    }
}

// round 8
// speedup vs baseline: 2.6996x; 2.5600x over previous
#include <cuda_runtime.h>
#include <cuda_bf16.h>
#include <stdint.h>
#include <math.h>

#define B_ 4096
#define D_ 128
#define K_ 4096
#define E_ 1024
#define H_ 2048
#define V_ 64

typedef __nv_bfloat16 bf16;

// ---------------- scratch (static device globals; no allocation) ----------------
__device__ float g_s[(size_t)B_ * K_];                       // diff, logits (fp32)
__device__ __align__(256) bf16 g_ph[(size_t)B_ * K_];        // p hi (score, then att)
__device__ __align__(256) bf16 g_pl[(size_t)B_ * K_];        // p lo
__device__ __align__(256) bf16 g_eh[(size_t)B_ * E_];
__device__ __align__(256) bf16 g_el[(size_t)B_ * E_];
__device__ __align__(256) bf16 g_hh[(size_t)B_ * H_];
__device__ __align__(256) bf16 g_hl[(size_t)B_ * H_];
__device__ __align__(256) bf16 g_weh[(size_t)E_ * K_];       // W_embed^T hi  [E,K]
__device__ __align__(256) bf16 g_wel[(size_t)E_ * K_];
__device__ __align__(256) bf16 g_whh[(size_t)H_ * E_];       // W_hidden^T    [H,E]
__device__ __align__(256) bf16 g_whl[(size_t)H_ * E_];
__device__ __align__(256) bf16 g_wah[(size_t)K_ * H_];       // W_att^T       [K,H]
__device__ __align__(256) bf16 g_wal[(size_t)K_ * H_];
__device__ __align__(256) bf16 g_vth[(size_t)V_ * K_];       // values^T      [V,K]
__device__ __align__(256) bf16 g_vtl[(size_t)V_ * K_];
__device__ __align__(256) bf16 g_xh[(size_t)B_ * D_];
__device__ __align__(256) bf16 g_xl[(size_t)B_ * D_];
__device__ __align__(256) bf16 g_kh[(size_t)K_ * D_];
__device__ __align__(256) bf16 g_kl[(size_t)K_ * D_];
__device__ float g_part[(size_t)4 * B_ * V_];                // split-K partials
__device__ float g_x2[B_];
__device__ float g_k2[K_];
__device__ float g_rsc[B_];

// ---------------- helpers ----------------
__device__ __forceinline__ uint32_t smem_u32(const void* p) {
    uint32_t a;
    asm("{ .reg .u64 t; cvta.to.shared.u64 t, %1; cvt.u32.u64 %0, t; }" : "=r"(a) : "l"(p));
    return a;
}
__device__ __forceinline__ void split_bf16(float v, bf16& h, bf16& l) {
    h = __float2bfloat16(v);
    l = __float2bfloat16(v - __bfloat162float(h));
}
__device__ __forceinline__ uint32_t pack2(bf16 a, bf16 b) {
    __nv_bfloat162 t(a, b);
    return *(uint32_t*)&t;
}

#define MMA_BF16(d, a, b)                                                      \
    asm volatile(                                                              \
        "mma.sync.aligned.m16n8k16.row.col.f32.bf16.bf16.f32 "                 \
        "{%0,%1,%2,%3}, {%4,%5,%6,%7}, {%8,%9}, {%0,%1,%2,%3};\n"              \
        : "+f"(d[0]), "+f"(d[1]), "+f"(d[2]), "+f"(d[3])                       \
        : "r"(a[0]), "r"(a[1]), "r"(a[2]), "r"(a[3]), "r"(b[0]), "r"(b[1]))

#define LDSM4(r, addr)                                                         \
    asm volatile("ldmatrix.sync.aligned.m8n8.x4.shared.b16 {%0,%1,%2,%3}, [%4];" \
        : "=r"((r)[0]), "=r"((r)[1]), "=r"((r)[2]), "=r"((r)[3]) : "r"(addr))

// stage NBYTES of a bf16 K-major tile (rows of 128B = 64 bf16) into SW128-swizzled smem
template<int NBYTES>
__device__ __forceinline__ void stage_cp(uint32_t dst, const bf16* src, int Kd) {
    const char* base = (const char*)src;
    int off = threadIdx.x * 16;
    #pragma unroll
    for (int it = 0; it < NBYTES / 4096; ++it, off += 4096) {
        int row = off >> 7;
        int kb  = off & 127;
        const char* g = base + (size_t)row * ((size_t)Kd * 2) + kb;
        uint32_t d = dst + (uint32_t)(off ^ ((off >> 3) & 0x70));
        asm volatile("cp.async.cg.shared.global [%0], [%1], 16;" :: "r"(d), "l"(g));
    }
}

// ---------------- mma.sync GEMM, hi/lo bf16 3-term, K-major A and B ----------------
// D[m][n] = sum_k A[m][k]*B[n][k].  BK = 64 fixed.  256 threads, warps 4(M) x 2(N).
// epi is a RUNTIME selector (keeps template instantiation count low).
enum { EPI_NONE = 0, EPI_DIST = 1, EPI_RELU_BIAS = 2, EPI_BIAS = 3, EPI_SRELU_BIAS = 4 };

template<int BM, int BN>
__global__ void __launch_bounds__(256)
tc_gemm(const bf16* __restrict__ Ah, const bf16* __restrict__ Al,
        const bf16* __restrict__ Bh, const bf16* __restrict__ Bl,
        float* __restrict__ Cf, bf16* __restrict__ Ch, bf16* __restrict__ Cl,
        int N, int Kd, int Kslice, int epi,
        const float* __restrict__ aux0, const float* __restrict__ aux1,
        const float* __restrict__ bias)
{
    constexpr int WM = BM / 4, WN = BN / 2;
    constexpr int MF = WM / 16, NF = WN / 8, NB = NF / 2;
    constexpr int ABYTES = BM * 128, BBYTES = BN * 128;
    constexpr int STAGE = 2 * (ABYTES + BBYTES);

    extern __shared__ char smem[];
    uint32_t sb = smem_u32(smem);
    const int tid = threadIdx.x, warp = tid >> 5, lane = tid & 31;
    const int gq = lane >> 2, tq = lane & 3;
    const int wm = (warp >> 1) * WM;
    const int wn = (warp & 1) * WN;
    const int rowBase = blockIdx.y * BM;
    const int colBase = blockIdx.x * BN;
    const int kstart  = blockIdx.z * Kslice;
    const int KT = Kslice / 64;

    if (epi == EPI_NONE) Cf += (size_t)blockIdx.z * ((size_t)B_ * BN);

    const bf16* Abh = Ah + (size_t)rowBase * Kd + kstart;
    const bf16* Abl = Al + (size_t)rowBase * Kd + kstart;
    const bf16* Bbh = Bh + (size_t)colBase * Kd + kstart;
    const bf16* Bbl = Bl + (size_t)colBase * Kd + kstart;

    // per-lane ldmatrix offsets: lane supplies row (lane&15) of a 16-row block,
    // k-half (lane>>4).  swizzled addr = row*128 + (kb ^ ((row&7)<<4))
    const int lr = lane & 15, lh = (lane >> 4) * 16;
    int aoff[MF], axr[MF], boff[NB], bxr[NB];
    #pragma unroll
    for (int fm = 0; fm < MF; ++fm) {
        int r = wm + fm * 16 + lr;
        aoff[fm] = r * 128; axr[fm] = (r & 7) << 4;
    }
    #pragma unroll
    for (int nb = 0; nb < NB; ++nb) {
        int r = wn + nb * 16 + lr;
        boff[nb] = r * 128; bxr[nb] = (r & 7) << 4;
    }

    float acc[MF][NF][4];
    #pragma unroll
    for (int i = 0; i < MF; ++i)
        #pragma unroll
        for (int j = 0; j < NF; ++j)
            #pragma unroll
            for (int c = 0; c < 4; ++c) acc[i][j][c] = 0.f;

    // ---- 2-stage cp.async pipeline ----
    #define STAGE_ALL(kt, buf) do {                                            \
        uint32_t d0 = sb + (buf) * STAGE;                                      \
        stage_cp<ABYTES>(d0,                    Abh + (kt) * 64, Kd);          \
        stage_cp<ABYTES>(d0 + ABYTES,           Abl + (kt) * 64, Kd);          \
        stage_cp<BBYTES>(d0 + 2 * ABYTES,           Bbh + (kt) * 64, Kd);      \
        stage_cp<BBYTES>(d0 + 2 * ABYTES + BBYTES,  Bbl + (kt) * 64, Kd);      \
    } while (0)

    STAGE_ALL(0, 0);
    asm volatile("cp.async.commit_group;" ::: "memory");

    for (int kt = 0; kt < KT; ++kt) {
        if (kt + 1 < KT) {
            STAGE_ALL(kt + 1, (kt + 1) & 1);
            asm volatile("cp.async.commit_group;" ::: "memory");
            asm volatile("cp.async.wait_group 1;" ::: "memory");
        } else {
            asm volatile("cp.async.wait_group 0;" ::: "memory");
        }
        __syncthreads();

        const uint32_t base = sb + (kt & 1) * STAGE;
        const uint32_t Ahb = base, Alb = base + ABYTES;
        const uint32_t Bhb = base + 2 * ABYTES, Blb = Bhb + BBYTES;

        #pragma unroll
        for (int ks = 0; ks < 4; ++ks) {
            const int kb = ks * 32 + lh;
            uint32_t ah[MF][4], al[MF][4];
            #pragma unroll
            for (int fm = 0; fm < MF; ++fm) {
                LDSM4(ah[fm], Ahb + aoff[fm] + (kb ^ axr[fm]));
                LDSM4(al[fm], Alb + aoff[fm] + (kb ^ axr[fm]));
            }
            #pragma unroll
            for (int nb = 0; nb < NB; ++nb) {
                uint32_t b4h[4], b4l[4];
                LDSM4(b4h, Bhb + boff[nb] + (kb ^ bxr[nb]));
                LDSM4(b4l, Blb + boff[nb] + (kb ^ bxr[nb]));
                #pragma unroll
                for (int odd = 0; odd < 2; ++odd) {
                    const int fn = nb * 2 + odd;
                    uint32_t bbh[2] = { b4h[odd], b4h[odd + 2] };
                    uint32_t bbl[2] = { b4l[odd], b4l[odd + 2] };
                    #pragma unroll
                    for (int fm = 0; fm < MF; ++fm) {
                        MMA_BF16(acc[fm][fn], ah[fm], bbh);
                        MMA_BF16(acc[fm][fn], ah[fm], bbl);
                        MMA_BF16(acc[fm][fn], al[fm], bbh);
                    }
                }
            }
        }
        __syncthreads();
    }

    // ---- epilogue (runtime-selected; cold path) ----
    #pragma unroll
    for (int fm = 0; fm < MF; ++fm) {
        #pragma unroll
        for (int half = 0; half < 2; ++half) {
            const int row = rowBase + wm + fm * 16 + gq + half * 8;
            float r0 = 0.f;
            if (epi == EPI_DIST || epi == EPI_SRELU_BIAS) r0 = aux0[row];
            #pragma unroll
            for (int fn = 0; fn < NF; ++fn) {
                const int col = colBase + wn + fn * 8 + tq * 2;
                float v0 = acc[fm][fn][half * 2 + 0];
                float v1 = acc[fm][fn][half * 2 + 1];
                if (epi == EPI_DIST) {
                    v0 = sqrtf(fmaxf(r0 + aux1[col]     - 2.f * v0, 0.f));
                    v1 = sqrtf(fmaxf(r0 + aux1[col + 1] - 2.f * v1, 0.f));
                } else if (epi == EPI_RELU_BIAS) {
                    v0 = fmaxf(v0 + bias[col], 0.f);
                    v1 = fmaxf(v1 + bias[col + 1], 0.f);
                } else if (epi == EPI_SRELU_BIAS) {
                    v0 = fmaxf(fmaf(v0, r0, bias[col]), 0.f);
                    v1 = fmaxf(fmaf(v1, r0, bias[col + 1]), 0.f);
                } else if (epi == EPI_BIAS) {
                    v0 += bias[col];
                    v1 += bias[col + 1];
                }
                if (epi == EPI_RELU_BIAS || epi == EPI_SRELU_BIAS) {
                    bf16 h0, l0, h1, l1;
                    split_bf16(v0, h0, l0);
                    split_bf16(v1, h1, l1);
                    *(uint32_t*)&Ch[(size_t)row * N + col] = pack2(h0, h1);
                    *(uint32_t*)&Cl[(size_t)row * N + col] = pack2(l0, l1);
                } else {
                    float2 o; o.x = v0; o.y = v1;
                    *(float2*)&Cf[(size_t)row * N + col] = o;
                }
            }
        }
    }
}

// ---------------- pre/post kernels ----------------
__global__ void sqnorm_kernel(const float* __restrict__ m, float* __restrict__ out, int rows) {
    int warp = (blockIdx.x * blockDim.x + threadIdx.x) >> 5;
    int lane = threadIdx.x & 31;
    if (warp >= rows) return;
    const float* r = m + (size_t)warp * D_;
    float s = 0.f;
    #pragma unroll
    for (int i = lane; i < D_; i += 32) { float v = r[i]; s += v * v; }
    #pragma unroll
    for (int o = 16; o; o >>= 1) s += __shfl_xor_sync(0xffffffffu, s, o);
    if (lane == 0) out[warp] = s;
}

__global__ void split_kernel(const float* __restrict__ in, bf16* __restrict__ oh,
                             bf16* __restrict__ ol, int n4) {
    int i = blockIdx.x * blockDim.x + threadIdx.x;
    if (i >= n4) return;
    float4 v = ((const float4*)in)[i];
    bf16 h0, l0, h1, l1, h2, l2, h3, l3;
    split_bf16(v.x, h0, l0); split_bf16(v.y, h1, l1);
    split_bf16(v.z, h2, l2); split_bf16(v.w, h3, l3);
    ((uint2*)oh)[i] = make_uint2(pack2(h0, h1), pack2(h2, h3));
    ((uint2*)ol)[i] = make_uint2(pack2(l0, l1), pack2(l2, l3));
}

// in [R,C] fp32 row-major -> out [C,R] bf16 hi/lo
__global__ void transpose_split(const float* __restrict__ in, bf16* __restrict__ oh,
                                bf16* __restrict__ ol, int R, int C) {
    __shared__ float t[32][33];
    int cb = blockIdx.x * 32, rb = blockIdx.y * 32;
    int tx = threadIdx.x, ty = threadIdx.y;
    #pragma unroll
    for (int i = 0; i < 32; i += 8)
        t[ty + i][tx] = in[(size_t)(rb + ty + i) * C + cb + tx];
    __syncthreads();
    #pragma unroll
    for (int i = 0; i < 32; i += 8) {
        float v = t[tx][ty + i];
        bf16 h, l;
        split_bf16(v, h, l);
        oh[(size_t)(cb + ty + i) * R + rb + tx] = h;
        ol[(size_t)(cb + ty + i) * R + rb + tx] = l;
    }
}

// score: p = exp(-10*diff/rowmax) (unnormalized, hi/lo) + 1/sum
__global__ void __launch_bounds__(256) score_kernel(const float* __restrict__ s,
                                                    bf16* __restrict__ ph, bf16* __restrict__ pl,
                                                    float* __restrict__ rsc) {
    const int row = blockIdx.x;
    const float* p = s + (size_t)row * K_;
    const int tid = threadIdx.x;
    constexpr int PT = K_ / 256;
    float v[PT];
    float mx = 0.f;
    #pragma unroll
    for (int i = 0; i < PT; ++i) { v[i] = p[tid + i * 256]; mx = fmaxf(mx, v[i]); }
    __shared__ float red[256];
    red[tid] = mx; __syncthreads();
    #pragma unroll
    for (int o = 128; o; o >>= 1) { if (tid < o) red[tid] = fmaxf(red[tid], red[tid + o]); __syncthreads(); }
    mx = red[0];
    __syncthreads();
    const float scale = -10.f / mx;
    float sum = 0.f;
    #pragma unroll
    for (int i = 0; i < PT; ++i) { v[i] = __expf(v[i] * scale); sum += v[i]; }
    red[tid] = sum; __syncthreads();
    #pragma unroll
    for (int o = 128; o; o >>= 1) { if (tid < o) red[tid] += red[tid + o]; __syncthreads(); }
    #pragma unroll
    for (int i = 0; i < PT; ++i) {
        bf16 h, l;
        split_bf16(v[i], h, l);
        ph[(size_t)row * K_ + tid + i * 256] = h;
        pl[(size_t)row * K_ + tid + i * 256] = l;
    }
    if (tid == 0) rsc[row] = 1.f / red[0];
}

// softmax: p = exp(l - rowmax) (unnormalized, hi/lo) + 1/sum
__global__ void __launch_bounds__(256) softmax_kernel(const float* __restrict__ s,
                                                      bf16* __restrict__ ph, bf16* __restrict__ pl,
                                                      float* __restrict__ rsc) {
    const int row = blockIdx.x;
    const float* p = s + (size_t)row * K_;
    const int tid = threadIdx.x;
    constexpr int PT = K_ / 256;
    float v[PT];
    float mx = -3.402823466e38f;
    #pragma unroll
    for (int i = 0; i < PT; ++i) { v[i] = p[tid + i * 256]; mx = fmaxf(mx, v[i]); }
    __shared__ float red[256];
    red[tid] = mx; __syncthreads();
    #pragma unroll
    for (int o = 128; o; o >>= 1) { if (tid < o) red[tid] = fmaxf(red[tid], red[tid + o]); __syncthreads(); }
    mx = red[0];
    __syncthreads();
    float sum = 0.f;
    #pragma unroll
    for (int i = 0; i < PT; ++i) { v[i] = __expf(v[i] - mx); sum += v[i]; }
    red[tid] = sum; __syncthreads();
    #pragma unroll
    for (int o = 128; o; o >>= 1) { if (tid < o) red[tid] += red[tid + o]; __syncthreads(); }
    #pragma unroll
    for (int i = 0; i < PT; ++i) {
        bf16 h, l;
        split_bf16(v[i], h, l);
        ph[(size_t)row * K_ + tid + i * 256] = h;
        pl[(size_t)row * K_ + tid + i * 256] = l;
    }
    if (tid == 0) rsc[row] = 1.f / red[0];
}

// out[b][v] = rsc[b] * sum_j part[j][b][v]
__global__ void reduce_out(const float* __restrict__ part, const float* __restrict__ rsc,
                           float* __restrict__ out) {
    int i = blockIdx.x * blockDim.x + threadIdx.x;
    constexpr int BV = B_ * V_;
    if (i >= BV) return;
    float v = part[i] + part[i + BV] + part[i + 2 * BV] + part[i + 3 * BV];
    out[i] = v * rsc[i / V_];
}

// ---------------- launch ----------------
extern "C" void kernel_launch(void* const* d_in, const int* in_sizes, int n_in,
                              void* d_out, int out_size) {
    const float* x        = (const float*)d_in[0];
    const float* keys     = (const float*)d_in[1];
    const float* values   = (const float*)d_in[2];
    const float* W_embed  = (const float*)d_in[3];
    const float* b_embed  = (const float*)d_in[4];
    const float* W_hidden = (const float*)d_in[5];
    const float* b_hidden = (const float*)d_in[6];
    const float* W_att    = (const float*)d_in[7];
    const float* b_att    = (const float*)d_in[8];
    float* out = (float*)d_out;

    float *s, *x2, *k2, *rsc, *part;
    bf16 *pch, *pcl, *eh, *el, *hh, *hl;
    bf16 *weh, *wel, *whh, *whl, *wah, *wal, *vth, *vtl, *xh, *xl, *kh, *kl;
    cudaGetSymbolAddress((void**)&s, g_s);
    cudaGetSymbolAddress((void**)&pch, g_ph);  cudaGetSymbolAddress((void**)&pcl, g_pl);
    cudaGetSymbolAddress((void**)&eh, g_eh);   cudaGetSymbolAddress((void**)&el, g_el);
    cudaGetSymbolAddress((void**)&hh, g_hh);   cudaGetSymbolAddress((void**)&hl, g_hl);
    cudaGetSymbolAddress((void**)&weh, g_weh); cudaGetSymbolAddress((void**)&wel, g_wel);
    cudaGetSymbolAddress((void**)&whh, g_whh); cudaGetSymbolAddress((void**)&whl, g_whl);
    cudaGetSymbolAddress((void**)&wah, g_wah); cudaGetSymbolAddress((void**)&wal, g_wal);
    cudaGetSymbolAddress((void**)&vth, g_vth); cudaGetSymbolAddress((void**)&vtl, g_vtl);
    cudaGetSymbolAddress((void**)&xh, g_xh);   cudaGetSymbolAddress((void**)&xl, g_xl);
    cudaGetSymbolAddress((void**)&kh, g_kh);   cudaGetSymbolAddress((void**)&kl, g_kl);
    cudaGetSymbolAddress((void**)&part, g_part);
    cudaGetSymbolAddress((void**)&x2, g_x2);
    cudaGetSymbolAddress((void**)&k2, g_k2);
    cudaGetSymbolAddress((void**)&rsc, g_rsc);

    // smem: 2 stages x 2(hi/lo) x (BM+BN)*128 bytes
    constexpr int SMEM_BIG = 2 * 2 * ((256 + 128) * 128);   // 196608
    constexpr int SMEM_SML = 2 * 2 * ((128 + 64) * 128);    //  98304
    cudaFuncSetAttribute((const void*)tc_gemm<256, 128>, cudaFuncAttributeMaxDynamicSharedMemorySize, SMEM_BIG);
    cudaFuncSetAttribute((const void*)tc_gemm<128, 64>,  cudaFuncAttributeMaxDynamicSharedMemorySize, SMEM_SML);

    // 0. preprocessing: norms, splits, weight transposes
    sqnorm_kernel<<<B_ / 8, 256>>>(x, x2, B_);
    sqnorm_kernel<<<K_ / 8, 256>>>(keys, k2, K_);
    split_kernel<<<(B_ * D_ / 4 + 255) / 256, 256>>>(x, xh, xl, B_ * D_ / 4);
    split_kernel<<<(K_ * D_ / 4 + 255) / 256, 256>>>(keys, kh, kl, K_ * D_ / 4);
    {
        dim3 blk(32, 8);
        transpose_split<<<dim3(E_ / 32, K_ / 32), blk>>>(W_embed, weh, wel, K_, E_);
        transpose_split<<<dim3(H_ / 32, E_ / 32), blk>>>(W_hidden, whh, whl, E_, H_);
        transpose_split<<<dim3(K_ / 32, H_ / 32), blk>>>(W_att, wah, wal, H_, K_);
        transpose_split<<<dim3(V_ / 32, K_ / 32), blk>>>(values, vth, vtl, K_, V_);
    }

    // 1. diff -> g_s (fp32)
    tc_gemm<256, 128><<<dim3(K_ / 128, B_ / 256, 1), 256, SMEM_BIG>>>(
        xh, xl, kh, kl, s, nullptr, nullptr, K_, D_, D_, EPI_DIST, x2, k2, nullptr);

    // 2. score p (hi/lo) + 1/sum
    score_kernel<<<B_, 256>>>(s, pch, pcl, rsc);

    // 3. e = relu(p @ We * rsc + b_embed) -> hi/lo
    tc_gemm<256, 128><<<dim3(E_ / 128, B_ / 256, 1), 256, SMEM_BIG>>>(
        pch, pcl, weh, wel, nullptr, eh, el, E_, K_, K_, EPI_SRELU_BIAS, rsc, nullptr, b_embed);

    // 4. h = relu(e @ Wh + b_hidden) -> hi/lo
    tc_gemm<256, 128><<<dim3(H_ / 128, B_ / 256, 1), 256, SMEM_BIG>>>(
        eh, el, whh, whl, nullptr, hh, hl, H_, E_, E_, EPI_RELU_BIAS, nullptr, nullptr, b_hidden);

    // 5. logits = h @ Wa + b_att -> g_s (fp32)
    tc_gemm<256, 128><<<dim3(K_ / 128, B_ / 256, 1), 256, SMEM_BIG>>>(
        hh, hl, wah, wal, s, nullptr, nullptr, K_, H_, H_, EPI_BIAS, nullptr, nullptr, b_att);

    // 6. softmax p (hi/lo) + 1/sum
    softmax_kernel<<<B_, 256>>>(s, pch, pcl, rsc);

    // 7. out partials (split-K x4), then reduce * rsc
    tc_gemm<128, 64><<<dim3(1, B_ / 128, 4), 256, SMEM_SML>>>(
        pch, pcl, vth, vtl, part, nullptr, nullptr, V_, K_, K_ / 4, EPI_NONE, nullptr, nullptr, nullptr);
    reduce_out<<<(B_ * V_ + 255) / 256, 256>>>(part, rsc, out);
}

// round 9
// speedup vs baseline: 2.7057x; 1.0023x over previous
#include <cuda_runtime.h>
#include <cuda_bf16.h>
#include <stdint.h>
#include <math.h>

#define B_ 4096
#define D_ 128
#define K_ 4096
#define E_ 1024
#define H_ 2048
#define V_ 64

typedef __nv_bfloat16 bf16;

// ---------------- scratch (static device globals; no allocation) ----------------
__device__ float g_s[(size_t)B_ * K_];                       // diff, logits (fp32)
__device__ __align__(256) bf16 g_ph[(size_t)B_ * K_];        // p hi (score, then att)
__device__ __align__(256) bf16 g_pl[(size_t)B_ * K_];        // p lo
__device__ __align__(256) bf16 g_eh[(size_t)B_ * E_];
__device__ __align__(256) bf16 g_el[(size_t)B_ * E_];
__device__ __align__(256) bf16 g_hh[(size_t)B_ * H_];
__device__ __align__(256) bf16 g_hl[(size_t)B_ * H_];
__device__ __align__(256) bf16 g_weh[(size_t)E_ * K_];       // W_embed^T hi  [E,K]
__device__ __align__(256) bf16 g_wel[(size_t)E_ * K_];
__device__ __align__(256) bf16 g_whh[(size_t)H_ * E_];       // W_hidden^T    [H,E]
__device__ __align__(256) bf16 g_whl[(size_t)H_ * E_];
__device__ __align__(256) bf16 g_wah[(size_t)K_ * H_];       // W_att^T       [K,H]
__device__ __align__(256) bf16 g_wal[(size_t)K_ * H_];
__device__ __align__(256) bf16 g_vth[(size_t)V_ * K_];       // values^T      [V,K]
__device__ __align__(256) bf16 g_vtl[(size_t)V_ * K_];
__device__ __align__(256) bf16 g_xh[(size_t)B_ * D_];
__device__ __align__(256) bf16 g_xl[(size_t)B_ * D_];
__device__ __align__(256) bf16 g_kh[(size_t)K_ * D_];
__device__ __align__(256) bf16 g_kl[(size_t)K_ * D_];
__device__ float g_part[(size_t)4 * B_ * V_];                // split-K partials
__device__ float g_x2[B_];
__device__ float g_k2[K_];
__device__ float g_rsc[B_];

// ---------------- helpers ----------------
__device__ __forceinline__ uint32_t smem_u32(const void* p) {
    uint32_t a;
    asm("{ .reg .u64 t; cvta.to.shared.u64 t, %1; cvt.u32.u64 %0, t; }" : "=r"(a) : "l"(p));
    return a;
}
__device__ __forceinline__ void split_bf16(float v, bf16& h, bf16& l) {
    h = __float2bfloat16(v);
    l = __float2bfloat16(v - __bfloat162float(h));
}
__device__ __forceinline__ uint32_t pack2(bf16 a, bf16 b) {
    __nv_bfloat162 t(a, b);
    return *(uint32_t*)&t;
}

#define MMA_BF16(d, a, b)                                                      \
    asm volatile(                                                              \
        "mma.sync.aligned.m16n8k16.row.col.f32.bf16.bf16.f32 "                 \
        "{%0,%1,%2,%3}, {%4,%5,%6,%7}, {%8,%9}, {%0,%1,%2,%3};\n"              \
        : "+f"(d[0]), "+f"(d[1]), "+f"(d[2]), "+f"(d[3])                       \
        : "r"(a[0]), "r"(a[1]), "r"(a[2]), "r"(a[3]), "r"(b[0]), "r"(b[1]))

#define LDSM4(r, addr)                                                         \
    asm volatile("ldmatrix.sync.aligned.m8n8.x4.shared.b16 {%0,%1,%2,%3}, [%4];" \
        : "=r"((r)[0]), "=r"((r)[1]), "=r"((r)[2]), "=r"((r)[3]) : "r"(addr))

// stage NBYTES of a bf16 K-major tile (rows of 128B = 64 bf16) into SW128-swizzled smem
template<int NBYTES, int NT>
__device__ __forceinline__ void stage_cp(uint32_t dst, const bf16* src, int Kd) {
    const char* base = (const char*)src;
    int off = threadIdx.x * 16;
    #pragma unroll
    for (int it = 0; it < NBYTES / (NT * 16); ++it, off += NT * 16) {
        int row = off >> 7;
        int kb  = off & 127;
        const char* g = base + (size_t)row * ((size_t)Kd * 2) + kb;
        uint32_t d = dst + (uint32_t)(off ^ ((off >> 3) & 0x70));
        asm volatile("cp.async.cg.shared.global [%0], [%1], 16;" :: "r"(d), "l"(g));
    }
}

// ---------------- mma.sync GEMM, hi/lo bf16 3-term, K-major A and B ----------------
// D[m][n] = sum_k A[m][k]*B[n][k].  BK = 64 fixed.  WRM x WRN warps.
// epi is a RUNTIME selector (keeps template instantiation count low).
enum { EPI_NONE = 0, EPI_DIST = 1, EPI_RELU_BIAS = 2, EPI_BIAS = 3, EPI_SRELU_BIAS = 4 };

template<int BM, int BN, int WRM, int WRN>
__global__ void __launch_bounds__(WRM * WRN * 32)
tc_gemm(const bf16* __restrict__ Ah, const bf16* __restrict__ Al,
        const bf16* __restrict__ Bh, const bf16* __restrict__ Bl,
        float* __restrict__ Cf, bf16* __restrict__ Ch, bf16* __restrict__ Cl,
        int N, int Kd, int Kslice, int epi,
        const float* __restrict__ aux0, const float* __restrict__ aux1,
        const float* __restrict__ bias)
{
    constexpr int NT = WRM * WRN * 32;
    constexpr int WM = BM / WRM, WN = BN / WRN;
    constexpr int MF = WM / 16, NF = WN / 8, NB = NF / 2;
    constexpr int ABYTES = BM * 128, BBYTES = BN * 128;
    constexpr int STAGE = 2 * (ABYTES + BBYTES);

    extern __shared__ char smem[];
    uint32_t sb = smem_u32(smem);
    const int tid = threadIdx.x, warp = tid >> 5, lane = tid & 31;
    const int gq = lane >> 2, tq = lane & 3;
    const int wm = (warp / WRN) * WM;
    const int wn = (warp % WRN) * WN;
    const int rowBase = blockIdx.y * BM;
    const int colBase = blockIdx.x * BN;
    const int kstart  = blockIdx.z * Kslice;
    const int KT = Kslice / 64;

    if (epi == EPI_NONE) Cf += (size_t)blockIdx.z * ((size_t)B_ * BN);

    const bf16* Abh = Ah + (size_t)rowBase * Kd + kstart;
    const bf16* Abl = Al + (size_t)rowBase * Kd + kstart;
    const bf16* Bbh = Bh + (size_t)colBase * Kd + kstart;
    const bf16* Bbl = Bl + (size_t)colBase * Kd + kstart;

    // per-lane ldmatrix offsets: lane supplies row (lane&15) of a 16-row block,
    // k-half (lane>>4).  swizzled addr = row*128 + (kb ^ ((row&7)<<4))
    const int lr = lane & 15, lh = (lane >> 4) * 16;
    int aoff[MF], axr[MF], boff[NB], bxr[NB];
    #pragma unroll
    for (int fm = 0; fm < MF; ++fm) {
        int r = wm + fm * 16 + lr;
        aoff[fm] = r * 128; axr[fm] = (r & 7) << 4;
    }
    #pragma unroll
    for (int nb = 0; nb < NB; ++nb) {
        int r = wn + nb * 16 + lr;
        boff[nb] = r * 128; bxr[nb] = (r & 7) << 4;
    }

    float acc[MF][NF][4];
    #pragma unroll
    for (int i = 0; i < MF; ++i)
        #pragma unroll
        for (int j = 0; j < NF; ++j)
            #pragma unroll
            for (int c = 0; c < 4; ++c) acc[i][j][c] = 0.f;

    // ---- 2-stage cp.async pipeline ----
    #define STAGE_ALL(kt, buf) do {                                            \
        uint32_t d0 = sb + (buf) * STAGE;                                      \
        stage_cp<ABYTES, NT>(d0,                    Abh + (kt) * 64, Kd);      \
        stage_cp<ABYTES, NT>(d0 + ABYTES,           Abl + (kt) * 64, Kd);      \
        stage_cp<BBYTES, NT>(d0 + 2 * ABYTES,           Bbh + (kt) * 64, Kd);  \
        stage_cp<BBYTES, NT>(d0 + 2 * ABYTES + BBYTES,  Bbl + (kt) * 64, Kd);  \
    } while (0)

    STAGE_ALL(0, 0);
    asm volatile("cp.async.commit_group;" ::: "memory");

    for (int kt = 0; kt < KT; ++kt) {
        if (kt + 1 < KT) {
            STAGE_ALL(kt + 1, (kt + 1) & 1);
            asm volatile("cp.async.commit_group;" ::: "memory");
            asm volatile("cp.async.wait_group 1;" ::: "memory");
        } else {
            asm volatile("cp.async.wait_group 0;" ::: "memory");
        }
        __syncthreads();

        const uint32_t base = sb + (kt & 1) * STAGE;
        const uint32_t Ahb = base, Alb = base + ABYTES;
        const uint32_t Bhb = base + 2 * ABYTES, Blb = Bhb + BBYTES;

        #pragma unroll
        for (int ks = 0; ks < 4; ++ks) {
            const int kb = ks * 32 + lh;
            uint32_t ah[MF][4], al[MF][4];
            #pragma unroll
            for (int fm = 0; fm < MF; ++fm) {
                LDSM4(ah[fm], Ahb + aoff[fm] + (kb ^ axr[fm]));
                LDSM4(al[fm], Alb + aoff[fm] + (kb ^ axr[fm]));
            }
            #pragma unroll
            for (int nb = 0; nb < NB; ++nb) {
                uint32_t b4h[4], b4l[4];
                LDSM4(b4h, Bhb + boff[nb] + (kb ^ bxr[nb]));
                LDSM4(b4l, Blb + boff[nb] + (kb ^ bxr[nb]));
                #pragma unroll
                for (int odd = 0; odd < 2; ++odd) {
                    const int fn = nb * 2 + odd;
                    uint32_t bbh[2] = { b4h[odd], b4h[odd + 2] };
                    uint32_t bbl[2] = { b4l[odd], b4l[odd + 2] };
                    #pragma unroll
                    for (int fm = 0; fm < MF; ++fm) {
                        MMA_BF16(acc[fm][fn], ah[fm], bbh);
                        MMA_BF16(acc[fm][fn], ah[fm], bbl);
                        MMA_BF16(acc[fm][fn], al[fm], bbh);
                    }
                }
            }
        }
        __syncthreads();
    }

    // ---- epilogue (runtime-selected; cold path) ----
    #pragma unroll
    for (int fm = 0; fm < MF; ++fm) {
        #pragma unroll
        for (int half = 0; half < 2; ++half) {
            const int row = rowBase + wm + fm * 16 + gq + half * 8;
            float r0 = 0.f;
            if (epi == EPI_DIST || epi == EPI_SRELU_BIAS) r0 = aux0[row];
            #pragma unroll
            for (int fn = 0; fn < NF; ++fn) {
                const int col = colBase + wn + fn * 8 + tq * 2;
                float v0 = acc[fm][fn][half * 2 + 0];
                float v1 = acc[fm][fn][half * 2 + 1];
                if (epi == EPI_DIST) {
                    v0 = sqrtf(fmaxf(r0 + aux1[col]     - 2.f * v0, 0.f));
                    v1 = sqrtf(fmaxf(r0 + aux1[col + 1] - 2.f * v1, 0.f));
                } else if (epi == EPI_RELU_BIAS) {
                    v0 = fmaxf(v0 + bias[col], 0.f);
                    v1 = fmaxf(v1 + bias[col + 1], 0.f);
                } else if (epi == EPI_SRELU_BIAS) {
                    v0 = fmaxf(fmaf(v0, r0, bias[col]), 0.f);
                    v1 = fmaxf(fmaf(v1, r0, bias[col + 1]), 0.f);
                } else if (epi == EPI_BIAS) {
                    v0 += bias[col];
                    v1 += bias[col + 1];
                }
                if (epi == EPI_RELU_BIAS || epi == EPI_SRELU_BIAS) {
                    bf16 h0, l0, h1, l1;
                    split_bf16(v0, h0, l0);
                    split_bf16(v1, h1, l1);
                    *(uint32_t*)&Ch[(size_t)row * N + col] = pack2(h0, h1);
                    *(uint32_t*)&Cl[(size_t)row * N + col] = pack2(l0, l1);
                } else {
                    float2 o; o.x = v0; o.y = v1;
                    *(float2*)&Cf[(size_t)row * N + col] = o;
                }
            }
        }
    }
}

// ---------------- pre/post kernels ----------------
__global__ void sqnorm_kernel(const float* __restrict__ m, float* __restrict__ out, int rows) {
    int warp = (blockIdx.x * blockDim.x + threadIdx.x) >> 5;
    int lane = threadIdx.x & 31;
    if (warp >= rows) return;
    const float* r = m + (size_t)warp * D_;
    float s = 0.f;
    #pragma unroll
    for (int i = lane; i < D_; i += 32) { float v = r[i]; s += v * v; }
    #pragma unroll
    for (int o = 16; o; o >>= 1) s += __shfl_xor_sync(0xffffffffu, s, o);
    if (lane == 0) out[warp] = s;
}

__global__ void split_kernel(const float* __restrict__ in, bf16* __restrict__ oh,
                             bf16* __restrict__ ol, int n4) {
    int i = blockIdx.x * blockDim.x + threadIdx.x;
    if (i >= n4) return;
    float4 v = ((const float4*)in)[i];
    bf16 h0, l0, h1, l1, h2, l2, h3, l3;
    split_bf16(v.x, h0, l0); split_bf16(v.y, h1, l1);
    split_bf16(v.z, h2, l2); split_bf16(v.w, h3, l3);
    ((uint2*)oh)[i] = make_uint2(pack2(h0, h1), pack2(h2, h3));
    ((uint2*)ol)[i] = make_uint2(pack2(l0, l1), pack2(l2, l3));
}

// in [R,C] fp32 row-major -> out [C,R] bf16 hi/lo
__global__ void transpose_split(const float* __restrict__ in, bf16* __restrict__ oh,
                                bf16* __restrict__ ol, int R, int C) {
    __shared__ float t[32][33];
    int cb = blockIdx.x * 32, rb = blockIdx.y * 32;
    int tx = threadIdx.x, ty = threadIdx.y;
    #pragma unroll
    for (int i = 0; i < 32; i += 8)
        t[ty + i][tx] = in[(size_t)(rb + ty + i) * C + cb + tx];
    __syncthreads();
    #pragma unroll
    for (int i = 0; i < 32; i += 8) {
        float v = t[tx][ty + i];
        bf16 h, l;
        split_bf16(v, h, l);
        oh[(size_t)(cb + ty + i) * R + rb + tx] = h;
        ol[(size_t)(cb + ty + i) * R + rb + tx] = l;
    }
}

// score: p = exp(-10*diff/rowmax) (unnormalized, hi/lo) + 1/sum
__global__ void __launch_bounds__(256) score_kernel(const float* __restrict__ s,
                                                    bf16* __restrict__ ph, bf16* __restrict__ pl,
                                                    float* __restrict__ rsc) {
    const int row = blockIdx.x;
    const float* p = s + (size_t)row * K_;
    const int tid = threadIdx.x;
    constexpr int PT = K_ / 256;
    float v[PT];
    float mx = 0.f;
    #pragma unroll
    for (int i = 0; i < PT; ++i) { v[i] = p[tid + i * 256]; mx = fmaxf(mx, v[i]); }
    __shared__ float red[256];
    red[tid] = mx; __syncthreads();
    #pragma unroll
    for (int o = 128; o; o >>= 1) { if (tid < o) red[tid] = fmaxf(red[tid], red[tid + o]); __syncthreads(); }
    mx = red[0];
    __syncthreads();
    const float scale = -10.f / mx;
    float sum = 0.f;
    #pragma unroll
    for (int i = 0; i < PT; ++i) { v[i] = __expf(v[i] * scale); sum += v[i]; }
    red[tid] = sum; __syncthreads();
    #pragma unroll
    for (int o = 128; o; o >>= 1) { if (tid < o) red[tid] += red[tid + o]; __syncthreads(); }
    #pragma unroll
    for (int i = 0; i < PT; ++i) {
        bf16 h, l;
        split_bf16(v[i], h, l);
        ph[(size_t)row * K_ + tid + i * 256] = h;
        pl[(size_t)row * K_ + tid + i * 256] = l;
    }
    if (tid == 0) rsc[row] = 1.f / red[0];
}

// softmax: p = exp(l - rowmax) (unnormalized, hi/lo) + 1/sum
__global__ void __launch_bounds__(256) softmax_kernel(const float* __restrict__ s,
                                                      bf16* __restrict__ ph, bf16* __restrict__ pl,
                                                      float* __restrict__ rsc) {
    const int row = blockIdx.x;
    const float* p = s + (size_t)row * K_;
    const int tid = threadIdx.x;
    constexpr int PT = K_ / 256;
    float v[PT];
    float mx = -3.402823466e38f;
    #pragma unroll
    for (int i = 0; i < PT; ++i) { v[i] = p[tid + i * 256]; mx = fmaxf(mx, v[i]); }
    __shared__ float red[256];
    red[tid] = mx; __syncthreads();
    #pragma unroll
    for (int o = 128; o; o >>= 1) { if (tid < o) red[tid] = fmaxf(red[tid], red[tid + o]); __syncthreads(); }
    mx = red[0];
    __syncthreads();
    float sum = 0.f;
    #pragma unroll
    for (int i = 0; i < PT; ++i) { v[i] = __expf(v[i] - mx); sum += v[i]; }
    red[tid] = sum; __syncthreads();
    #pragma unroll
    for (int o = 128; o; o >>= 1) { if (tid < o) red[tid] += red[tid + o]; __syncthreads(); }
    #pragma unroll
    for (int i = 0; i < PT; ++i) {
        bf16 h, l;
        split_bf16(v[i], h, l);
        ph[(size_t)row * K_ + tid + i * 256] = h;
        pl[(size_t)row * K_ + tid + i * 256] = l;
    }
    if (tid == 0) rsc[row] = 1.f / red[0];
}

// out[b][v] = rsc[b] * sum_j part[j][b][v]
__global__ void reduce_out(const float* __restrict__ part, const float* __restrict__ rsc,
                           float* __restrict__ out) {
    int i = blockIdx.x * blockDim.x + threadIdx.x;
    constexpr int BV = B_ * V_;
    if (i >= BV) return;
    float v = part[i] + part[i + BV] + part[i + 2 * BV] + part[i + 3 * BV];
    out[i] = v * rsc[i / V_];
}

// ---------------- launch ----------------
extern "C" void kernel_launch(void* const* d_in, const int* in_sizes, int n_in,
                              void* d_out, int out_size) {
    const float* x        = (const float*)d_in[0];
    const float* keys     = (const float*)d_in[1];
    const float* values   = (const float*)d_in[2];
    const float* W_embed  = (const float*)d_in[3];
    const float* b_embed  = (const float*)d_in[4];
    const float* W_hidden = (const float*)d_in[5];
    const float* b_hidden = (const float*)d_in[6];
    const float* W_att    = (const float*)d_in[7];
    const float* b_att    = (const float*)d_in[8];
    float* out = (float*)d_out;

    float *s, *x2, *k2, *rsc, *part;
    bf16 *pch, *pcl, *eh, *el, *hh, *hl;
    bf16 *weh, *wel, *whh, *whl, *wah, *wal, *vth, *vtl, *xh, *xl, *kh, *kl;
    cudaGetSymbolAddress((void**)&s, g_s);
    cudaGetSymbolAddress((void**)&pch, g_ph);  cudaGetSymbolAddress((void**)&pcl, g_pl);
    cudaGetSymbolAddress((void**)&eh, g_eh);   cudaGetSymbolAddress((void**)&el, g_el);
    cudaGetSymbolAddress((void**)&hh, g_hh);   cudaGetSymbolAddress((void**)&hl, g_hl);
    cudaGetSymbolAddress((void**)&weh, g_weh); cudaGetSymbolAddress((void**)&wel, g_wel);
    cudaGetSymbolAddress((void**)&whh, g_whh); cudaGetSymbolAddress((void**)&whl, g_whl);
    cudaGetSymbolAddress((void**)&wah, g_wah); cudaGetSymbolAddress((void**)&wal, g_wal);
    cudaGetSymbolAddress((void**)&vth, g_vth); cudaGetSymbolAddress((void**)&vtl, g_vtl);
    cudaGetSymbolAddress((void**)&xh, g_xh);   cudaGetSymbolAddress((void**)&xl, g_xl);
    cudaGetSymbolAddress((void**)&kh, g_kh);   cudaGetSymbolAddress((void**)&kl, g_kl);
    cudaGetSymbolAddress((void**)&part, g_part);
    cudaGetSymbolAddress((void**)&x2, g_x2);
    cudaGetSymbolAddress((void**)&k2, g_k2);
    cudaGetSymbolAddress((void**)&rsc, g_rsc);

    // smem: 2 stages x 2(hi/lo) x (BM+BN)*128 bytes
    constexpr int SMEM_BIG = 2 * 2 * ((256 + 128) * 128);   // 196608
    constexpr int SMEM_SML = 2 * 2 * ((128 + 64) * 128);    //  98304
    cudaFuncSetAttribute((const void*)tc_gemm<256, 128, 4, 4>, cudaFuncAttributeMaxDynamicSharedMemorySize, SMEM_BIG);
    cudaFuncSetAttribute((const void*)tc_gemm<128, 64, 4, 2>,  cudaFuncAttributeMaxDynamicSharedMemorySize, SMEM_SML);

    // 0. preprocessing: norms, splits, weight transposes
    sqnorm_kernel<<<B_ / 8, 256>>>(x, x2, B_);
    sqnorm_kernel<<<K_ / 8, 256>>>(keys, k2, K_);
    split_kernel<<<(B_ * D_ / 4 + 255) / 256, 256>>>(x, xh, xl, B_ * D_ / 4);
    split_kernel<<<(K_ * D_ / 4 + 255) / 256, 256>>>(keys, kh, kl, K_ * D_ / 4);
    {
        dim3 blk(32, 8);
        transpose_split<<<dim3(E_ / 32, K_ / 32), blk>>>(W_embed, weh, wel, K_, E_);
        transpose_split<<<dim3(H_ / 32, E_ / 32), blk>>>(W_hidden, whh, whl, E_, H_);
        transpose_split<<<dim3(K_ / 32, H_ / 32), blk>>>(W_att, wah, wal, H_, K_);
        transpose_split<<<dim3(V_ / 32, K_ / 32), blk>>>(values, vth, vtl, K_, V_);
    }

    // 1. diff -> g_s (fp32)
    tc_gemm<256, 128, 4, 4><<<dim3(K_ / 128, B_ / 256, 1), 512, SMEM_BIG>>>(
        xh, xl, kh, kl, s, nullptr, nullptr, K_, D_, D_, EPI_DIST, x2, k2, nullptr);

    // 2. score p (hi/lo) + 1/sum
    score_kernel<<<B_, 256>>>(s, pch, pcl, rsc);

    // 3. e = relu(p @ We * rsc + b_embed) -> hi/lo
    tc_gemm<256, 128, 4, 4><<<dim3(E_ / 128, B_ / 256, 1), 512, SMEM_BIG>>>(
        pch, pcl, weh, wel, nullptr, eh, el, E_, K_, K_, EPI_SRELU_BIAS, rsc, nullptr, b_embed);

    // 4. h = relu(e @ Wh + b_hidden) -> hi/lo
    tc_gemm<256, 128, 4, 4><<<dim3(H_ / 128, B_ / 256, 1), 512, SMEM_BIG>>>(
        eh, el, whh, whl, nullptr, hh, hl, H_, E_, E_, EPI_RELU_BIAS, nullptr, nullptr, b_hidden);

    // 5. logits = h @ Wa + b_att -> g_s (fp32)
    tc_gemm<256, 128, 4, 4><<<dim3(K_ / 128, B_ / 256, 1), 512, SMEM_BIG>>>(
        hh, hl, wah, wal, s, nullptr, nullptr, K_, H_, H_, EPI_BIAS, nullptr, nullptr, b_att);

    // 6. softmax p (hi/lo) + 1/sum
    softmax_kernel<<<B_, 256>>>(s, pch, pcl, rsc);

    // 7. out partials (split-K x4), then reduce * rsc
    tc_gemm<128, 64, 4, 2><<<dim3(1, B_ / 128, 4), 256, SMEM_SML>>>(
        pch, pcl, vth, vtl, part, nullptr, nullptr, V_, K_, K_ / 4, EPI_NONE, nullptr, nullptr, nullptr);
    reduce_out<<<(B_ * V_ + 255) / 256, 256>>>(part, rsc, out);
}

// round 10
// speedup vs baseline: 3.6964x; 1.3661x over previous
#include <cuda_runtime.h>
#include <cuda_fp16.h>
#include <stdint.h>
#include <math.h>

#define B_ 4096
#define D_ 128
#define K_ 4096
#define E_ 1024
#define H_ 2048
#define V_ 64

// tensor scales (exact powers of 2; folded into epilogues)
#define SP_  64.0f      // score p scale
#define SE_  8192.0f    // e scale
#define SH_  8192.0f    // h scale
#define SP2_ 64.0f      // softmax p scale

typedef __half f16;

// ---------------- scratch (static device globals; no allocation) ----------------
__device__ float g_s[(size_t)B_ * K_];                       // diff, logits (fp32)
__device__ __align__(256) f16 g_ph[(size_t)B_ * K_];         // p hi (score, then att)
__device__ __align__(256) f16 g_pl[(size_t)B_ * K_];         // p lo
__device__ __align__(256) f16 g_eh[(size_t)B_ * E_];
__device__ __align__(256) f16 g_el[(size_t)B_ * E_];
__device__ __align__(256) f16 g_hh[(size_t)B_ * H_];
__device__ __align__(256) f16 g_hl[(size_t)B_ * H_];
__device__ __align__(256) f16 g_we[(size_t)E_ * K_];         // W_embed^T  [E,K] fp16
__device__ __align__(256) f16 g_wh[(size_t)H_ * E_];         // W_hidden^T [H,E]
__device__ __align__(256) f16 g_wa[(size_t)K_ * H_];         // W_att^T    [K,H]
__device__ __align__(256) f16 g_vt[(size_t)V_ * K_];         // values^T   [V,K]
__device__ __align__(256) f16 g_xh[(size_t)B_ * D_];
__device__ __align__(256) f16 g_xl[(size_t)B_ * D_];
__device__ __align__(256) f16 g_kc[(size_t)K_ * D_];         // keys fp16
__device__ float g_part[(size_t)4 * B_ * V_];                // split-K partials
__device__ float g_x2[B_];
__device__ float g_k2[K_];
__device__ float g_rsc[B_];

// ---------------- helpers ----------------
__device__ __forceinline__ uint32_t smem_u32(const void* p) {
    uint32_t a;
    asm("{ .reg .u64 t; cvta.to.shared.u64 t, %1; cvt.u32.u64 %0, t; }" : "=r"(a) : "l"(p));
    return a;
}
__device__ __forceinline__ void split_f16(float v, f16& h, f16& l) {
    h = __float2half(v);
    l = __float2half(v - __half2float(h));
}
__device__ __forceinline__ uint32_t pack2h(f16 a, f16 b) {
    __half2 t = __halves2half2(a, b);
    return *(uint32_t*)&t;
}

#define MMA_F16(d, a, b)                                                       \
    asm volatile(                                                              \
        "mma.sync.aligned.m16n8k16.row.col.f32.f16.f16.f32 "                   \
        "{%0,%1,%2,%3}, {%4,%5,%6,%7}, {%8,%9}, {%0,%1,%2,%3};\n"              \
        : "+f"(d[0]), "+f"(d[1]), "+f"(d[2]), "+f"(d[3])                       \
        : "r"(a[0]), "r"(a[1]), "r"(a[2]), "r"(a[3]), "r"(b[0]), "r"(b[1]))

#define LDSM4(r, addr)                                                         \
    asm volatile("ldmatrix.sync.aligned.m8n8.x4.shared.b16 {%0,%1,%2,%3}, [%4];" \
        : "=r"((r)[0]), "=r"((r)[1]), "=r"((r)[2]), "=r"((r)[3]) : "r"(addr))

// stage NBYTES of a f16 K-major tile (rows of 128B = 64 f16) into SW128-swizzled smem
template<int NBYTES, int NT>
__device__ __forceinline__ void stage_cp(uint32_t dst, const f16* src, int Kd) {
    const char* base = (const char*)src;
    int off = threadIdx.x * 16;
    #pragma unroll
    for (int it = 0; it < NBYTES / (NT * 16); ++it, off += NT * 16) {
        int row = off >> 7;
        int kb  = off & 127;
        const char* g = base + (size_t)row * ((size_t)Kd * 2) + kb;
        uint32_t d = dst + (uint32_t)(off ^ ((off >> 3) & 0x70));
        asm volatile("cp.async.cg.shared.global [%0], [%1], 16;" :: "r"(d), "l"(g));
    }
}

// ---------------- mma.sync GEMM: A = hi+lo fp16 (2-term), B = fp16, K-major ----------------
// D[m][n] = sum_k (Ah+Al)[m][k] * B[n][k].  BK = 64 fixed.  WRM x WRN warps.
enum { EPI_NONE = 0, EPI_DIST = 1, EPI_RELU_BIAS = 2, EPI_BIAS = 3, EPI_SRELU_BIAS = 4 };

template<int BM, int BN, int WRM, int WRN>
__global__ void __launch_bounds__(WRM * WRN * 32)
tc_gemm(const f16* __restrict__ Ah, const f16* __restrict__ Al,
        const f16* __restrict__ Bh,
        float* __restrict__ Cf, f16* __restrict__ Ch, f16* __restrict__ Cl,
        int N, int Kd, int Kslice, int epi, float aScale, float outScale,
        const float* __restrict__ aux0, const float* __restrict__ aux1,
        const float* __restrict__ bias)
{
    constexpr int NT = WRM * WRN * 32;
    constexpr int WM = BM / WRM, WN = BN / WRN;
    constexpr int MF = WM / 16, NF = WN / 8, NB = NF / 2;
    constexpr int ABYTES = BM * 128, BBYTES = BN * 128;
    constexpr int STAGE = 2 * ABYTES + BBYTES;

    extern __shared__ char smem[];
    uint32_t sb = smem_u32(smem);
    const int tid = threadIdx.x, warp = tid >> 5, lane = tid & 31;
    const int gq = lane >> 2, tq = lane & 3;
    const int wm = (warp / WRN) * WM;
    const int wn = (warp % WRN) * WN;
    const int rowBase = blockIdx.y * BM;
    const int colBase = blockIdx.x * BN;
    const int kstart  = blockIdx.z * Kslice;
    const int KT = Kslice / 64;

    if (epi == EPI_NONE) Cf += (size_t)blockIdx.z * ((size_t)B_ * BN);

    const f16* Abh = Ah + (size_t)rowBase * Kd + kstart;
    const f16* Abl = Al + (size_t)rowBase * Kd + kstart;
    const f16* Bbh = Bh + (size_t)colBase * Kd + kstart;

    // per-lane ldmatrix offsets: swizzled addr = row*128 + (kb ^ ((row&7)<<4))
    const int lr = lane & 15, lh = (lane >> 4) * 16;
    int aoff[MF], axr[MF], boff[NB], bxr[NB];
    #pragma unroll
    for (int fm = 0; fm < MF; ++fm) {
        int r = wm + fm * 16 + lr;
        aoff[fm] = r * 128; axr[fm] = (r & 7) << 4;
    }
    #pragma unroll
    for (int nb = 0; nb < NB; ++nb) {
        int r = wn + nb * 16 + lr;
        boff[nb] = r * 128; bxr[nb] = (r & 7) << 4;
    }

    float acc[MF][NF][4];
    #pragma unroll
    for (int i = 0; i < MF; ++i)
        #pragma unroll
        for (int j = 0; j < NF; ++j)
            #pragma unroll
            for (int c = 0; c < 4; ++c) acc[i][j][c] = 0.f;

    // ---- 2-stage cp.async pipeline ----
    #define STAGE_ALL(kt, buf) do {                                            \
        uint32_t d0 = sb + (buf) * STAGE;                                      \
        stage_cp<ABYTES, NT>(d0,              Abh + (kt) * 64, Kd);            \
        stage_cp<ABYTES, NT>(d0 + ABYTES,     Abl + (kt) * 64, Kd);            \
        stage_cp<BBYTES, NT>(d0 + 2 * ABYTES, Bbh + (kt) * 64, Kd);            \
    } while (0)

    STAGE_ALL(0, 0);
    asm volatile("cp.async.commit_group;" ::: "memory");

    for (int kt = 0; kt < KT; ++kt) {
        if (kt + 1 < KT) {
            STAGE_ALL(kt + 1, (kt + 1) & 1);
            asm volatile("cp.async.commit_group;" ::: "memory");
            asm volatile("cp.async.wait_group 1;" ::: "memory");
        } else {
            asm volatile("cp.async.wait_group 0;" ::: "memory");
        }
        __syncthreads();

        const uint32_t base = sb + (kt & 1) * STAGE;
        const uint32_t Ahb = base, Alb = base + ABYTES;
        const uint32_t Bhb = base + 2 * ABYTES;

        #pragma unroll
        for (int ks = 0; ks < 4; ++ks) {
            const int kb = ks * 32 + lh;
            uint32_t ah[MF][4], al[MF][4];
            #pragma unroll
            for (int fm = 0; fm < MF; ++fm) {
                LDSM4(ah[fm], Ahb + aoff[fm] + (kb ^ axr[fm]));
                LDSM4(al[fm], Alb + aoff[fm] + (kb ^ axr[fm]));
            }
            #pragma unroll
            for (int nb = 0; nb < NB; ++nb) {
                uint32_t b4[4];
                LDSM4(b4, Bhb + boff[nb] + (kb ^ bxr[nb]));
                #pragma unroll
                for (int odd = 0; odd < 2; ++odd) {
                    const int fn = nb * 2 + odd;
                    uint32_t bb[2] = { b4[odd], b4[odd + 2] };
                    #pragma unroll
                    for (int fm = 0; fm < MF; ++fm) {
                        MMA_F16(acc[fm][fn], ah[fm], bb);
                        MMA_F16(acc[fm][fn], al[fm], bb);
                    }
                }
            }
        }
        __syncthreads();
    }

    // ---- epilogue (runtime-selected; cold path) ----
    #pragma unroll
    for (int fm = 0; fm < MF; ++fm) {
        #pragma unroll
        for (int half = 0; half < 2; ++half) {
            const int row = rowBase + wm + fm * 16 + gq + half * 8;
            float r0 = 0.f;
            if (epi == EPI_DIST) r0 = aux0[row];
            if (epi == EPI_SRELU_BIAS) r0 = aux0[row] * aScale;
            #pragma unroll
            for (int fn = 0; fn < NF; ++fn) {
                const int col = colBase + wn + fn * 8 + tq * 2;
                float v0 = acc[fm][fn][half * 2 + 0];
                float v1 = acc[fm][fn][half * 2 + 1];
                if (epi == EPI_DIST) {
                    v0 = sqrtf(fmaxf(r0 + aux1[col]     - 2.f * v0, 0.f));
                    v1 = sqrtf(fmaxf(r0 + aux1[col + 1] - 2.f * v1, 0.f));
                } else if (epi == EPI_RELU_BIAS) {
                    v0 = fmaxf(fmaf(v0, aScale, bias[col]), 0.f);
                    v1 = fmaxf(fmaf(v1, aScale, bias[col + 1]), 0.f);
                } else if (epi == EPI_SRELU_BIAS) {
                    v0 = fmaxf(fmaf(v0, r0, bias[col]), 0.f);
                    v1 = fmaxf(fmaf(v1, r0, bias[col + 1]), 0.f);
                } else if (epi == EPI_BIAS) {
                    v0 = fmaf(v0, aScale, bias[col]);
                    v1 = fmaf(v1, aScale, bias[col + 1]);
                }
                if (epi == EPI_RELU_BIAS || epi == EPI_SRELU_BIAS) {
                    f16 h0, l0, h1, l1;
                    split_f16(v0 * outScale, h0, l0);
                    split_f16(v1 * outScale, h1, l1);
                    *(uint32_t*)&Ch[(size_t)row * N + col] = pack2h(h0, h1);
                    *(uint32_t*)&Cl[(size_t)row * N + col] = pack2h(l0, l1);
                } else {
                    float2 o; o.x = v0; o.y = v1;
                    *(float2*)&Cf[(size_t)row * N + col] = o;
                }
            }
        }
    }
}

// ---------------- pre/post kernels ----------------
__global__ void sqnorm_kernel(const float* __restrict__ m, float* __restrict__ out, int rows) {
    int warp = (blockIdx.x * blockDim.x + threadIdx.x) >> 5;
    int lane = threadIdx.x & 31;
    if (warp >= rows) return;
    const float* r = m + (size_t)warp * D_;
    float s = 0.f;
    #pragma unroll
    for (int i = lane; i < D_; i += 32) { float v = r[i]; s += v * v; }
    #pragma unroll
    for (int o = 16; o; o >>= 1) s += __shfl_xor_sync(0xffffffffu, s, o);
    if (lane == 0) out[warp] = s;
}

// fp32 -> fp16 hi/lo (2-term), vectorized
__global__ void split2_kernel(const float* __restrict__ in, f16* __restrict__ oh,
                              f16* __restrict__ ol, int n4) {
    int i = blockIdx.x * blockDim.x + threadIdx.x;
    if (i >= n4) return;
    float4 v = ((const float4*)in)[i];
    f16 h0, l0, h1, l1, h2, l2, h3, l3;
    split_f16(v.x, h0, l0); split_f16(v.y, h1, l1);
    split_f16(v.z, h2, l2); split_f16(v.w, h3, l3);
    ((uint2*)oh)[i] = make_uint2(pack2h(h0, h1), pack2h(h2, h3));
    ((uint2*)ol)[i] = make_uint2(pack2h(l0, l1), pack2h(l2, l3));
}

// fp32 -> fp16 single, vectorized
__global__ void conv_kernel(const float* __restrict__ in, f16* __restrict__ o, int n4) {
    int i = blockIdx.x * blockDim.x + threadIdx.x;
    if (i >= n4) return;
    float4 v = ((const float4*)in)[i];
    ((uint2*)o)[i] = make_uint2(pack2h(__float2half(v.x), __float2half(v.y)),
                                pack2h(__float2half(v.z), __float2half(v.w)));
}

// in [R,C] fp32 row-major -> out [C,R] fp16 single
__global__ void transpose_h(const float* __restrict__ in, f16* __restrict__ o, int R, int C) {
    __shared__ float t[32][33];
    int cb = blockIdx.x * 32, rb = blockIdx.y * 32;
    int tx = threadIdx.x, ty = threadIdx.y;
    #pragma unroll
    for (int i = 0; i < 32; i += 8)
        t[ty + i][tx] = in[(size_t)(rb + ty + i) * C + cb + tx];
    __syncthreads();
    #pragma unroll
    for (int i = 0; i < 32; i += 8)
        o[(size_t)(cb + ty + i) * R + rb + tx] = __float2half(t[tx][ty + i]);
}

// score: p = exp(-10*diff/rowmax); store (p*SP_) hi/lo + rsc = 1/sum(p)
__global__ void __launch_bounds__(256) score_kernel(const float* __restrict__ s,
                                                    f16* __restrict__ ph, f16* __restrict__ pl,
                                                    float* __restrict__ rsc) {
    const int row = blockIdx.x;
    const float* p = s + (size_t)row * K_;
    const int tid = threadIdx.x;
    constexpr int PT = K_ / 256;
    float v[PT];
    float mx = 0.f;
    #pragma unroll
    for (int i = 0; i < PT; ++i) { v[i] = p[tid + i * 256]; mx = fmaxf(mx, v[i]); }
    __shared__ float red[256];
    red[tid] = mx; __syncthreads();
    #pragma unroll
    for (int o = 128; o; o >>= 1) { if (tid < o) red[tid] = fmaxf(red[tid], red[tid + o]); __syncthreads(); }
    mx = red[0];
    __syncthreads();
    const float scale = -10.f / mx;
    float sum = 0.f;
    #pragma unroll
    for (int i = 0; i < PT; ++i) { v[i] = __expf(v[i] * scale); sum += v[i]; }
    red[tid] = sum; __syncthreads();
    #pragma unroll
    for (int o = 128; o; o >>= 1) { if (tid < o) red[tid] += red[tid + o]; __syncthreads(); }
    #pragma unroll
    for (int i = 0; i < PT; ++i) {
        f16 h, l;
        split_f16(v[i] * SP_, h, l);
        ph[(size_t)row * K_ + tid + i * 256] = h;
        pl[(size_t)row * K_ + tid + i * 256] = l;
    }
    if (tid == 0) rsc[row] = 1.f / red[0];
}

// softmax: p = exp(l - rowmax); store (p*SP2_) hi/lo + rsc = 1/sum(p)
__global__ void __launch_bounds__(256) softmax_kernel(const float* __restrict__ s,
                                                      f16* __restrict__ ph, f16* __restrict__ pl,
                                                      float* __restrict__ rsc) {
    const int row = blockIdx.x;
    const float* p = s + (size_t)row * K_;
    const int tid = threadIdx.x;
    constexpr int PT = K_ / 256;
    float v[PT];
    float mx = -3.402823466e38f;
    #pragma unroll
    for (int i = 0; i < PT; ++i) { v[i] = p[tid + i * 256]; mx = fmaxf(mx, v[i]); }
    __shared__ float red[256];
    red[tid] = mx; __syncthreads();
    #pragma unroll
    for (int o = 128; o; o >>= 1) { if (tid < o) red[tid] = fmaxf(red[tid], red[tid + o]); __syncthreads(); }
    mx = red[0];
    __syncthreads();
    float sum = 0.f;
    #pragma unroll
    for (int i = 0; i < PT; ++i) { v[i] = __expf(v[i] - mx); sum += v[i]; }
    red[tid] = sum; __syncthreads();
    #pragma unroll
    for (int o = 128; o; o >>= 1) { if (tid < o) red[tid] += red[tid + o]; __syncthreads(); }
    #pragma unroll
    for (int i = 0; i < PT; ++i) {
        f16 h, l;
        split_f16(v[i] * SP2_, h, l);
        ph[(size_t)row * K_ + tid + i * 256] = h;
        pl[(size_t)row * K_ + tid + i * 256] = l;
    }
    if (tid == 0) rsc[row] = 1.f / red[0];
}

// out[b][v] = (rsc[b]/SP2_) * sum_j part[j][b][v]
__global__ void reduce_out(const float* __restrict__ part, const float* __restrict__ rsc,
                           float* __restrict__ out) {
    int i = blockIdx.x * blockDim.x + threadIdx.x;
    constexpr int BV = B_ * V_;
    if (i >= BV) return;
    float v = part[i] + part[i + BV] + part[i + 2 * BV] + part[i + 3 * BV];
    out[i] = v * rsc[i / V_] * (1.0f / SP2_);
}

// ---------------- launch ----------------
extern "C" void kernel_launch(void* const* d_in, const int* in_sizes, int n_in,
                              void* d_out, int out_size) {
    const float* x        = (const float*)d_in[0];
    const float* keys     = (const float*)d_in[1];
    const float* values   = (const float*)d_in[2];
    const float* W_embed  = (const float*)d_in[3];
    const float* b_embed  = (const float*)d_in[4];
    const float* W_hidden = (const float*)d_in[5];
    const float* b_hidden = (const float*)d_in[6];
    const float* W_att    = (const float*)d_in[7];
    const float* b_att    = (const float*)d_in[8];
    float* out = (float*)d_out;

    float *s, *x2, *k2, *rsc, *part;
    f16 *pch, *pcl, *eh, *el, *hh, *hl;
    f16 *we, *wh, *wa, *vt, *xh, *xl, *kc;
    cudaGetSymbolAddress((void**)&s, g_s);
    cudaGetSymbolAddress((void**)&pch, g_ph);  cudaGetSymbolAddress((void**)&pcl, g_pl);
    cudaGetSymbolAddress((void**)&eh, g_eh);   cudaGetSymbolAddress((void**)&el, g_el);
    cudaGetSymbolAddress((void**)&hh, g_hh);   cudaGetSymbolAddress((void**)&hl, g_hl);
    cudaGetSymbolAddress((void**)&we, g_we);
    cudaGetSymbolAddress((void**)&wh, g_wh);
    cudaGetSymbolAddress((void**)&wa, g_wa);
    cudaGetSymbolAddress((void**)&vt, g_vt);
    cudaGetSymbolAddress((void**)&xh, g_xh);   cudaGetSymbolAddress((void**)&xl, g_xl);
    cudaGetSymbolAddress((void**)&kc, g_kc);
    cudaGetSymbolAddress((void**)&part, g_part);
    cudaGetSymbolAddress((void**)&x2, g_x2);
    cudaGetSymbolAddress((void**)&k2, g_k2);
    cudaGetSymbolAddress((void**)&rsc, g_rsc);

    // smem: 2 stages x (2*BM + BN)*128 bytes
    constexpr int SMEM_BIG = 2 * ((2 * 256 + 128) * 128);   // 163840
    constexpr int SMEM_SML = 2 * ((2 * 128 + 64) * 128);    //  81920
    cudaFuncSetAttribute((const void*)tc_gemm<256, 128, 4, 4>, cudaFuncAttributeMaxDynamicSharedMemorySize, SMEM_BIG);
    cudaFuncSetAttribute((const void*)tc_gemm<128, 64, 4, 2>,  cudaFuncAttributeMaxDynamicSharedMemorySize, SMEM_SML);

    // 0. preprocessing: norms, converts, weight transposes
    sqnorm_kernel<<<B_ / 8, 256>>>(x, x2, B_);
    sqnorm_kernel<<<K_ / 8, 256>>>(keys, k2, K_);
    split2_kernel<<<(B_ * D_ / 4 + 255) / 256, 256>>>(x, xh, xl, B_ * D_ / 4);
    conv_kernel<<<(K_ * D_ / 4 + 255) / 256, 256>>>(keys, kc, K_ * D_ / 4);
    {
        dim3 blk(32, 8);
        transpose_h<<<dim3(E_ / 32, K_ / 32), blk>>>(W_embed, we, K_, E_);
        transpose_h<<<dim3(H_ / 32, E_ / 32), blk>>>(W_hidden, wh, E_, H_);
        transpose_h<<<dim3(K_ / 32, H_ / 32), blk>>>(W_att, wa, H_, K_);
        transpose_h<<<dim3(V_ / 32, K_ / 32), blk>>>(values, vt, K_, V_);
    }

    // 1. diff -> g_s (fp32)
    tc_gemm<256, 128, 4, 4><<<dim3(K_ / 128, B_ / 256, 1), 512, SMEM_BIG>>>(
        xh, xl, kc, s, nullptr, nullptr, K_, D_, D_, EPI_DIST, 1.f, 1.f, x2, k2, nullptr);

    // 2. score p (hi/lo, xSP_) + 1/sum
    score_kernel<<<B_, 256>>>(s, pch, pcl, rsc);

    // 3. e = relu(p @ We * rsc + b_embed); stored xSE_
    tc_gemm<256, 128, 4, 4><<<dim3(E_ / 128, B_ / 256, 1), 512, SMEM_BIG>>>(
        pch, pcl, we, nullptr, eh, el, E_, K_, K_, EPI_SRELU_BIAS, 1.f / SP_, SE_, rsc, nullptr, b_embed);

    // 4. h = relu(e @ Wh + b_hidden); acc scaled by 1/SE_, stored xSH_
    tc_gemm<256, 128, 4, 4><<<dim3(H_ / 128, B_ / 256, 1), 512, SMEM_BIG>>>(
        eh, el, wh, nullptr, hh, hl, H_, E_, E_, EPI_RELU_BIAS, 1.f / SE_, SH_, nullptr, nullptr, b_hidden);

    // 5. logits = h @ Wa / SH_ + b_att -> g_s (fp32)
    tc_gemm<256, 128, 4, 4><<<dim3(K_ / 128, B_ / 256, 1), 512, SMEM_BIG>>>(
        hh, hl, wa, s, nullptr, nullptr, K_, H_, H_, EPI_BIAS, 1.f / SH_, 1.f, nullptr, nullptr, b_att);

    // 6. softmax p (hi/lo, xSP2_) + 1/sum
    softmax_kernel<<<B_, 256>>>(s, pch, pcl, rsc);

    // 7. out partials (split-K x4), then reduce * rsc / SP2_
    tc_gemm<128, 64, 4, 2><<<dim3(1, B_ / 128, 4), 256, SMEM_SML>>>(
        pch, pcl, vt, part, nullptr, nullptr, V_, K_, K_ / 4, EPI_NONE, 1.f, 1.f, nullptr, nullptr, nullptr);
    reduce_out<<<(B_ * V_ + 255) / 256, 256>>>(part, rsc, out);
}

// round 11
// speedup vs baseline: 6.5727x; 1.7781x over previous
#include <cuda_runtime.h>
#include <cuda_fp16.h>
#include <stdint.h>
#include <math.h>

#define B_ 4096
#define D_ 128
#define K_ 4096
#define E_ 1024
#define H_ 2048
#define V_ 64

// tensor scales (exact powers of 2; folded into epilogues)
#define SP_  64.0f      // score p scale
#define SE_  8192.0f    // e scale
#define SH_  8192.0f    // h scale
#define SP2_ 64.0f      // softmax p scale

typedef __half f16;

// ---------------- scratch (static device globals; no allocation) ----------------
__device__ float g_s[(size_t)B_ * K_];                       // diff, logits (fp32)
__device__ __align__(256) f16 g_p[(size_t)B_ * K_];          // p (score, then att)
__device__ __align__(256) f16 g_e[(size_t)B_ * E_];
__device__ __align__(256) f16 g_h[(size_t)B_ * H_];
__device__ __align__(256) f16 g_we[(size_t)E_ * K_];         // W_embed^T  [E,K] fp16
__device__ __align__(256) f16 g_wh[(size_t)H_ * E_];         // W_hidden^T [H,E]
__device__ __align__(256) f16 g_wa[(size_t)K_ * H_];         // W_att^T    [K,H]
__device__ __align__(256) f16 g_vt[(size_t)V_ * K_];         // values^T   [V,K]
__device__ __align__(256) f16 g_xc[(size_t)B_ * D_];         // x fp16
__device__ __align__(256) f16 g_kc[(size_t)K_ * D_];         // keys fp16
__device__ float g_part[(size_t)4 * B_ * V_];                // split-K partials
__device__ float g_x2[B_];
__device__ float g_k2[K_];
__device__ float g_rsc[B_];

// ---------------- helpers ----------------
__device__ __forceinline__ uint32_t smem_u32(const void* p) {
    uint32_t a;
    asm("{ .reg .u64 t; cvta.to.shared.u64 t, %1; cvt.u32.u64 %0, t; }" : "=r"(a) : "l"(p));
    return a;
}
__device__ __forceinline__ uint32_t pack2h(f16 a, f16 b) {
    __half2 t = __halves2half2(a, b);
    return *(uint32_t*)&t;
}

#define MMA_F16(d, a, b)                                                       \
    asm volatile(                                                              \
        "mma.sync.aligned.m16n8k16.row.col.f32.f16.f16.f32 "                   \
        "{%0,%1,%2,%3}, {%4,%5,%6,%7}, {%8,%9}, {%0,%1,%2,%3};\n"              \
        : "+f"(d[0]), "+f"(d[1]), "+f"(d[2]), "+f"(d[3])                       \
        : "r"(a[0]), "r"(a[1]), "r"(a[2]), "r"(a[3]), "r"(b[0]), "r"(b[1]))

#define LDSM4(r, addr)                                                         \
    asm volatile("ldmatrix.sync.aligned.m8n8.x4.shared.b16 {%0,%1,%2,%3}, [%4];" \
        : "=r"((r)[0]), "=r"((r)[1]), "=r"((r)[2]), "=r"((r)[3]) : "r"(addr))

// stage NBYTES of a f16 K-major tile (rows of 128B = 64 f16) into SW128-swizzled smem
template<int NBYTES, int NT>
__device__ __forceinline__ void stage_cp(uint32_t dst, const f16* src, int Kd) {
    const char* base = (const char*)src;
    int off = threadIdx.x * 16;
    #pragma unroll
    for (int it = 0; it < NBYTES / (NT * 16); ++it, off += NT * 16) {
        int row = off >> 7;
        int kb  = off & 127;
        const char* g = base + (size_t)row * ((size_t)Kd * 2) + kb;
        uint32_t d = dst + (uint32_t)(off ^ ((off >> 3) & 0x70));
        asm volatile("cp.async.cg.shared.global [%0], [%1], 16;" :: "r"(d), "l"(g));
    }
}

// ---------------- mma.sync GEMM: A, B single fp16, K-major ----------------
// D[m][n] = sum_k A[m][k]*B[n][k].  BK = 64 fixed.  WRM x WRN warps.
enum { EPI_NONE = 0, EPI_DIST = 1, EPI_RELU_BIAS = 2, EPI_BIAS = 3, EPI_SRELU_BIAS = 4 };

template<int BM, int BN, int WRM, int WRN>
__global__ void __launch_bounds__(WRM * WRN * 32)
tc_gemm(const f16* __restrict__ Ah, const f16* __restrict__ Bh,
        float* __restrict__ Cf, f16* __restrict__ Ch,
        int N, int Kd, int Kslice, int epi, float aScale, float outScale,
        const float* __restrict__ aux0, const float* __restrict__ aux1,
        const float* __restrict__ bias)
{
    constexpr int NT = WRM * WRN * 32;
    constexpr int WM = BM / WRM, WN = BN / WRN;
    constexpr int MF = WM / 16, NF = WN / 8, NB = NF / 2;
    constexpr int ABYTES = BM * 128, BBYTES = BN * 128;
    constexpr int STAGE = ABYTES + BBYTES;

    extern __shared__ char smem[];
    uint32_t sb = smem_u32(smem);
    const int tid = threadIdx.x, warp = tid >> 5, lane = tid & 31;
    const int gq = lane >> 2, tq = lane & 3;
    const int wm = (warp / WRN) * WM;
    const int wn = (warp % WRN) * WN;
    const int rowBase = blockIdx.y * BM;
    const int colBase = blockIdx.x * BN;
    const int kstart  = blockIdx.z * Kslice;
    const int KT = Kslice / 64;

    if (epi == EPI_NONE) Cf += (size_t)blockIdx.z * ((size_t)B_ * BN);

    const f16* Abh = Ah + (size_t)rowBase * Kd + kstart;
    const f16* Bbh = Bh + (size_t)colBase * Kd + kstart;

    // per-lane ldmatrix offsets: swizzled addr = row*128 + (kb ^ ((row&7)<<4))
    const int lr = lane & 15, lh = (lane >> 4) * 16;
    int aoff[MF], axr[MF], boff[NB], bxr[NB];
    #pragma unroll
    for (int fm = 0; fm < MF; ++fm) {
        int r = wm + fm * 16 + lr;
        aoff[fm] = r * 128; axr[fm] = (r & 7) << 4;
    }
    #pragma unroll
    for (int nb = 0; nb < NB; ++nb) {
        int r = wn + nb * 16 + lr;
        boff[nb] = r * 128; bxr[nb] = (r & 7) << 4;
    }

    float acc[MF][NF][4];
    #pragma unroll
    for (int i = 0; i < MF; ++i)
        #pragma unroll
        for (int j = 0; j < NF; ++j)
            #pragma unroll
            for (int c = 0; c < 4; ++c) acc[i][j][c] = 0.f;

    // ---- 2-stage cp.async pipeline ----
    #define STAGE_ALL(kt, buf) do {                                            \
        uint32_t d0 = sb + (buf) * STAGE;                                      \
        stage_cp<ABYTES, NT>(d0,          Abh + (kt) * 64, Kd);                \
        stage_cp<BBYTES, NT>(d0 + ABYTES, Bbh + (kt) * 64, Kd);                \
    } while (0)

    STAGE_ALL(0, 0);
    asm volatile("cp.async.commit_group;" ::: "memory");

    for (int kt = 0; kt < KT; ++kt) {
        if (kt + 1 < KT) {
            STAGE_ALL(kt + 1, (kt + 1) & 1);
            asm volatile("cp.async.commit_group;" ::: "memory");
            asm volatile("cp.async.wait_group 1;" ::: "memory");
        } else {
            asm volatile("cp.async.wait_group 0;" ::: "memory");
        }
        __syncthreads();

        const uint32_t base = sb + (kt & 1) * STAGE;
        const uint32_t Ahb = base;
        const uint32_t Bhb = base + ABYTES;

        #pragma unroll
        for (int ks = 0; ks < 4; ++ks) {
            const int kb = ks * 32 + lh;
            uint32_t ah[MF][4];
            #pragma unroll
            for (int fm = 0; fm < MF; ++fm)
                LDSM4(ah[fm], Ahb + aoff[fm] + (kb ^ axr[fm]));
            #pragma unroll
            for (int nb = 0; nb < NB; ++nb) {
                uint32_t b4[4];
                LDSM4(b4, Bhb + boff[nb] + (kb ^ bxr[nb]));
                #pragma unroll
                for (int odd = 0; odd < 2; ++odd) {
                    const int fn = nb * 2 + odd;
                    uint32_t bb[2] = { b4[odd], b4[odd + 2] };
                    #pragma unroll
                    for (int fm = 0; fm < MF; ++fm)
                        MMA_F16(acc[fm][fn], ah[fm], bb);
                }
            }
        }
        __syncthreads();
    }

    // ---- epilogue (runtime-selected; cold path) ----
    #pragma unroll
    for (int fm = 0; fm < MF; ++fm) {
        #pragma unroll
        for (int half = 0; half < 2; ++half) {
            const int row = rowBase + wm + fm * 16 + gq + half * 8;
            float r0 = 0.f;
            if (epi == EPI_DIST) r0 = aux0[row];
            if (epi == EPI_SRELU_BIAS) r0 = aux0[row] * aScale;
            #pragma unroll
            for (int fn = 0; fn < NF; ++fn) {
                const int col = colBase + wn + fn * 8 + tq * 2;
                float v0 = acc[fm][fn][half * 2 + 0];
                float v1 = acc[fm][fn][half * 2 + 1];
                if (epi == EPI_DIST) {
                    v0 = sqrtf(fmaxf(r0 + aux1[col]     - 2.f * v0, 0.f));
                    v1 = sqrtf(fmaxf(r0 + aux1[col + 1] - 2.f * v1, 0.f));
                } else if (epi == EPI_RELU_BIAS) {
                    v0 = fmaxf(fmaf(v0, aScale, bias[col]), 0.f);
                    v1 = fmaxf(fmaf(v1, aScale, bias[col + 1]), 0.f);
                } else if (epi == EPI_SRELU_BIAS) {
                    v0 = fmaxf(fmaf(v0, r0, bias[col]), 0.f);
                    v1 = fmaxf(fmaf(v1, r0, bias[col + 1]), 0.f);
                } else if (epi == EPI_BIAS) {
                    v0 = fmaf(v0, aScale, bias[col]);
                    v1 = fmaf(v1, aScale, bias[col + 1]);
                }
                if (epi == EPI_RELU_BIAS || epi == EPI_SRELU_BIAS) {
                    *(uint32_t*)&Ch[(size_t)row * N + col] =
                        pack2h(__float2half(v0 * outScale), __float2half(v1 * outScale));
                } else {
                    float2 o; o.x = v0; o.y = v1;
                    *(float2*)&Cf[(size_t)row * N + col] = o;
                }
            }
        }
    }
}

// ---------------- pre/post kernels ----------------
__global__ void sqnorm_kernel(const float* __restrict__ m, float* __restrict__ out, int rows) {
    int warp = (blockIdx.x * blockDim.x + threadIdx.x) >> 5;
    int lane = threadIdx.x & 31;
    if (warp >= rows) return;
    const float* r = m + (size_t)warp * D_;
    float s = 0.f;
    #pragma unroll
    for (int i = lane; i < D_; i += 32) { float v = r[i]; s += v * v; }
    #pragma unroll
    for (int o = 16; o; o >>= 1) s += __shfl_xor_sync(0xffffffffu, s, o);
    if (lane == 0) out[warp] = s;
}

// fp32 -> fp16 single, vectorized
__global__ void conv_kernel(const float* __restrict__ in, f16* __restrict__ o, int n4) {
    int i = blockIdx.x * blockDim.x + threadIdx.x;
    if (i >= n4) return;
    float4 v = ((const float4*)in)[i];
    ((uint2*)o)[i] = make_uint2(pack2h(__float2half(v.x), __float2half(v.y)),
                                pack2h(__float2half(v.z), __float2half(v.w)));
}

// in [R,C] fp32 row-major -> out [C,R] fp16 single
__global__ void transpose_h(const float* __restrict__ in, f16* __restrict__ o, int R, int C) {
    __shared__ float t[32][33];
    int cb = blockIdx.x * 32, rb = blockIdx.y * 32;
    int tx = threadIdx.x, ty = threadIdx.y;
    #pragma unroll
    for (int i = 0; i < 32; i += 8)
        t[ty + i][tx] = in[(size_t)(rb + ty + i) * C + cb + tx];
    __syncthreads();
    #pragma unroll
    for (int i = 0; i < 32; i += 8)
        o[(size_t)(cb + ty + i) * R + rb + tx] = __float2half(t[tx][ty + i]);
}

// score: p = exp(-10*diff/rowmax); store (p*SP_) f16 + rsc = 1/sum(p)
__global__ void __launch_bounds__(256) score_kernel(const float* __restrict__ s,
                                                    f16* __restrict__ ph,
                                                    float* __restrict__ rsc) {
    const int row = blockIdx.x;
    const float* p = s + (size_t)row * K_;
    const int tid = threadIdx.x;
    constexpr int PT = K_ / 256;
    float v[PT];
    float mx = 0.f;
    #pragma unroll
    for (int i = 0; i < PT; ++i) { v[i] = p[tid + i * 256]; mx = fmaxf(mx, v[i]); }
    __shared__ float red[256];
    red[tid] = mx; __syncthreads();
    #pragma unroll
    for (int o = 128; o; o >>= 1) { if (tid < o) red[tid] = fmaxf(red[tid], red[tid + o]); __syncthreads(); }
    mx = red[0];
    __syncthreads();
    const float scale = -10.f / mx;
    float sum = 0.f;
    #pragma unroll
    for (int i = 0; i < PT; ++i) { v[i] = __expf(v[i] * scale); sum += v[i]; }
    red[tid] = sum; __syncthreads();
    #pragma unroll
    for (int o = 128; o; o >>= 1) { if (tid < o) red[tid] += red[tid + o]; __syncthreads(); }
    #pragma unroll
    for (int i = 0; i < PT; ++i)
        ph[(size_t)row * K_ + tid + i * 256] = __float2half(v[i] * SP_);
    if (tid == 0) rsc[row] = 1.f / red[0];
}

// softmax: p = exp(l - rowmax); store (p*SP2_) f16 + rsc = 1/sum(p)
__global__ void __launch_bounds__(256) softmax_kernel(const float* __restrict__ s,
                                                      f16* __restrict__ ph,
                                                      float* __restrict__ rsc) {
    const int row = blockIdx.x;
    const float* p = s + (size_t)row * K_;
    const int tid = threadIdx.x;
    constexpr int PT = K_ / 256;
    float v[PT];
    float mx = -3.402823466e38f;
    #pragma unroll
    for (int i = 0; i < PT; ++i) { v[i] = p[tid + i * 256]; mx = fmaxf(mx, v[i]); }
    __shared__ float red[256];
    red[tid] = mx; __syncthreads();
    #pragma unroll
    for (int o = 128; o; o >>= 1) { if (tid < o) red[tid] = fmaxf(red[tid], red[tid + o]); __syncthreads(); }
    mx = red[0];
    __syncthreads();
    float sum = 0.f;
    #pragma unroll
    for (int i = 0; i < PT; ++i) { v[i] = __expf(v[i] - mx); sum += v[i]; }
    red[tid] = sum; __syncthreads();
    #pragma unroll
    for (int o = 128; o; o >>= 1) { if (tid < o) red[tid] += red[tid + o]; __syncthreads(); }
    #pragma unroll
    for (int i = 0; i < PT; ++i)
        ph[(size_t)row * K_ + tid + i * 256] = __float2half(v[i] * SP2_);
    if (tid == 0) rsc[row] = 1.f / red[0];
}

// out[b][v] = (rsc[b]/SP2_) * sum_j part[j][b][v]
__global__ void reduce_out(const float* __restrict__ part, const float* __restrict__ rsc,
                           float* __restrict__ out) {
    int i = blockIdx.x * blockDim.x + threadIdx.x;
    constexpr int BV = B_ * V_;
    if (i >= BV) return;
    float v = part[i] + part[i + BV] + part[i + 2 * BV] + part[i + 3 * BV];
    out[i] = v * rsc[i / V_] * (1.0f / SP2_);
}

// ---------------- launch ----------------
extern "C" void kernel_launch(void* const* d_in, const int* in_sizes, int n_in,
                              void* d_out, int out_size) {
    const float* x        = (const float*)d_in[0];
    const float* keys     = (const float*)d_in[1];
    const float* values   = (const float*)d_in[2];
    const float* W_embed  = (const float*)d_in[3];
    const float* b_embed  = (const float*)d_in[4];
    const float* W_hidden = (const float*)d_in[5];
    const float* b_hidden = (const float*)d_in[6];
    const float* W_att    = (const float*)d_in[7];
    const float* b_att    = (const float*)d_in[8];
    float* out = (float*)d_out;

    float *s, *x2, *k2, *rsc, *part;
    f16 *pc, *ec, *hc, *we, *wh, *wa, *vt, *xc, *kc;
    cudaGetSymbolAddress((void**)&s, g_s);
    cudaGetSymbolAddress((void**)&pc, g_p);
    cudaGetSymbolAddress((void**)&ec, g_e);
    cudaGetSymbolAddress((void**)&hc, g_h);
    cudaGetSymbolAddress((void**)&we, g_we);
    cudaGetSymbolAddress((void**)&wh, g_wh);
    cudaGetSymbolAddress((void**)&wa, g_wa);
    cudaGetSymbolAddress((void**)&vt, g_vt);
    cudaGetSymbolAddress((void**)&xc, g_xc);
    cudaGetSymbolAddress((void**)&kc, g_kc);
    cudaGetSymbolAddress((void**)&part, g_part);
    cudaGetSymbolAddress((void**)&x2, g_x2);
    cudaGetSymbolAddress((void**)&k2, g_k2);
    cudaGetSymbolAddress((void**)&rsc, g_rsc);

    // smem: 2 stages x (BM + BN)*128 bytes
    constexpr int SMEM_BIG = 2 * ((256 + 128) * 128);   // 98304
    constexpr int SMEM_SML = 2 * ((128 + 64) * 128);    // 49152
    cudaFuncSetAttribute((const void*)tc_gemm<256, 128, 4, 4>, cudaFuncAttributeMaxDynamicSharedMemorySize, SMEM_BIG);
    cudaFuncSetAttribute((const void*)tc_gemm<128, 64, 4, 2>,  cudaFuncAttributeMaxDynamicSharedMemorySize, SMEM_SML);

    // 0. preprocessing: norms, converts, weight transposes
    sqnorm_kernel<<<B_ / 8, 256>>>(x, x2, B_);
    sqnorm_kernel<<<K_ / 8, 256>>>(keys, k2, K_);
    conv_kernel<<<(B_ * D_ / 4 + 255) / 256, 256>>>(x, xc, B_ * D_ / 4);
    conv_kernel<<<(K_ * D_ / 4 + 255) / 256, 256>>>(keys, kc, K_ * D_ / 4);
    {
        dim3 blk(32, 8);
        transpose_h<<<dim3(E_ / 32, K_ / 32), blk>>>(W_embed, we, K_, E_);
        transpose_h<<<dim3(H_ / 32, E_ / 32), blk>>>(W_hidden, wh, E_, H_);
        transpose_h<<<dim3(K_ / 32, H_ / 32), blk>>>(W_att, wa, H_, K_);
        transpose_h<<<dim3(V_ / 32, K_ / 32), blk>>>(values, vt, K_, V_);
    }

    // 1. diff -> g_s (fp32)
    tc_gemm<256, 128, 4, 4><<<dim3(K_ / 128, B_ / 256, 1), 512, SMEM_BIG>>>(
        xc, kc, s, nullptr, K_, D_, D_, EPI_DIST, 1.f, 1.f, x2, k2, nullptr);

    // 2. score p (xSP_) + 1/sum
    score_kernel<<<B_, 256>>>(s, pc, rsc);

    // 3. e = relu(p @ We * rsc + b_embed); stored xSE_
    tc_gemm<256, 128, 4, 4><<<dim3(E_ / 128, B_ / 256, 1), 512, SMEM_BIG>>>(
        pc, we, nullptr, ec, E_, K_, K_, EPI_SRELU_BIAS, 1.f / SP_, SE_, rsc, nullptr, b_embed);

    // 4. h = relu(e @ Wh + b_hidden); acc scaled by 1/SE_, stored xSH_
    tc_gemm<256, 128, 4, 4><<<dim3(H_ / 128, B_ / 256, 1), 512, SMEM_BIG>>>(
        ec, wh, nullptr, hc, H_, E_, E_, EPI_RELU_BIAS, 1.f / SE_, SH_, nullptr, nullptr, b_hidden);

    // 5. logits = h @ Wa / SH_ + b_att -> g_s (fp32)
    tc_gemm<256, 128, 4, 4><<<dim3(K_ / 128, B_ / 256, 1), 512, SMEM_BIG>>>(
        hc, wa, s, nullptr, K_, H_, H_, EPI_BIAS, 1.f / SH_, 1.f, nullptr, nullptr, b_att);

    // 6. softmax p (xSP2_) + 1/sum
    softmax_kernel<<<B_, 256>>>(s, pc, rsc);

    // 7. out partials (split-K x4), then reduce * rsc / SP2_
    tc_gemm<128, 64, 4, 2><<<dim3(1, B_ / 128, 4), 256, SMEM_SML>>>(
        pc, vt, part, nullptr, V_, K_, K_ / 4, EPI_NONE, 1.f, 1.f, nullptr, nullptr, nullptr);
    reduce_out<<<(B_ * V_ + 255) / 256, 256>>>(part, rsc, out);
}

// round 13
// speedup vs baseline: 6.6398x; 1.0102x over previous
#include <cuda_runtime.h>
#include <cuda_fp16.h>
#include <stdint.h>
#include <math.h>

#define B_ 4096
#define D_ 128
#define K_ 4096
#define E_ 1024
#define H_ 2048
#define V_ 64

// tensor scales (exact powers of 2; folded into epilogues)
#define SP_  64.0f      // score p scale
#define SE_  8192.0f    // e scale
#define SH_  8192.0f    // h scale
#define SP2_ 64.0f      // softmax p scale

typedef __half f16;

// ---------------- scratch (static device globals; no allocation) ----------------
__device__ float g_s[(size_t)B_ * K_];                       // diff, logits (fp32)
__device__ __align__(256) f16 g_p[(size_t)B_ * K_];          // p (score, then att)
__device__ __align__(256) f16 g_e[(size_t)B_ * E_];
__device__ __align__(256) f16 g_h[(size_t)B_ * H_];
__device__ __align__(256) f16 g_we[(size_t)E_ * K_];         // W_embed^T  [E,K] fp16
__device__ __align__(256) f16 g_wh[(size_t)H_ * E_];         // W_hidden^T [H,E]
__device__ __align__(256) f16 g_wa[(size_t)K_ * H_];         // W_att^T    [K,H]
__device__ __align__(256) f16 g_vt[(size_t)V_ * K_];         // values^T   [V,K]
__device__ __align__(256) f16 g_xc[(size_t)B_ * D_];         // x fp16
__device__ __align__(256) f16 g_kc[(size_t)K_ * D_];         // keys fp16
__device__ float g_part[(size_t)4 * B_ * V_];                // split-K partials
__device__ float g_x2[B_];
__device__ float g_k2[K_];
__device__ float g_rsc[B_];

// ---------------- helpers ----------------
__device__ __forceinline__ uint32_t smem_u32(const void* p) {
    uint32_t a;
    asm("{ .reg .u64 t; cvta.to.shared.u64 t, %1; cvt.u32.u64 %0, t; }" : "=r"(a) : "l"(p));
    return a;
}
__device__ __forceinline__ uint32_t pack2h(f16 a, f16 b) {
    __half2 t = __halves2half2(a, b);
    return *(uint32_t*)&t;
}

#define MMA_F16(d, a, b)                                                       \
    asm volatile(                                                              \
        "mma.sync.aligned.m16n8k16.row.col.f32.f16.f16.f32 "                   \
        "{%0,%1,%2,%3}, {%4,%5,%6,%7}, {%8,%9}, {%0,%1,%2,%3};\n"              \
        : "+f"(d[0]), "+f"(d[1]), "+f"(d[2]), "+f"(d[3])                       \
        : "r"(a[0]), "r"(a[1]), "r"(a[2]), "r"(a[3]), "r"(b[0]), "r"(b[1]))

#define LDSM4(r, addr)                                                         \
    asm volatile("ldmatrix.sync.aligned.m8n8.x4.shared.b16 {%0,%1,%2,%3}, [%4];" \
        : "=r"((r)[0]), "=r"((r)[1]), "=r"((r)[2]), "=r"((r)[3]) : "r"(addr))

// stage NBYTES of a f16 K-major tile (rows of 128B = 64 f16) into SW128-swizzled smem
template<int NBYTES, int NT>
__device__ __forceinline__ void stage_cp(uint32_t dst, const f16* src, int Kd) {
    const char* base = (const char*)src;
    int off = threadIdx.x * 16;
    #pragma unroll
    for (int it = 0; it < NBYTES / (NT * 16); ++it, off += NT * 16) {
        int row = off >> 7;
        int kb  = off & 127;
        const char* g = base + (size_t)row * ((size_t)Kd * 2) + kb;
        uint32_t d = dst + (uint32_t)(off ^ ((off >> 3) & 0x70));
        asm volatile("cp.async.cg.shared.global [%0], [%1], 16;" :: "r"(d), "l"(g));
    }
}

// ---------------- mma.sync GEMM: A, B single fp16, K-major ----------------
// D[m][n] = sum_k A[m][k]*B[n][k].  BK = 64 fixed.  WRM x WRN warps.
enum { EPI_NONE = 0, EPI_DIST = 1, EPI_RELU_BIAS = 2, EPI_BIAS = 3, EPI_SRELU_BIAS = 4 };

template<int BM, int BN, int WRM, int WRN>
__global__ void __launch_bounds__(WRM * WRN * 32)
tc_gemm(const f16* __restrict__ Ah, const f16* __restrict__ Bh,
        float* __restrict__ Cf, f16* __restrict__ Ch,
        int N, int Kd, int Kslice, int epi, float aScale, float outScale,
        const float* __restrict__ aux0, const float* __restrict__ aux1,
        const float* __restrict__ bias)
{
    constexpr int NT = WRM * WRN * 32;
    constexpr int WM = BM / WRM, WN = BN / WRN;
    constexpr int MF = WM / 16, NF = WN / 8, NB = NF / 2;
    constexpr int ABYTES = BM * 128, BBYTES = BN * 128;
    constexpr int STAGE = ABYTES + BBYTES;

    extern __shared__ char smem[];
    uint32_t sb = smem_u32(smem);
    const int tid = threadIdx.x, warp = tid >> 5, lane = tid & 31;
    const int gq = lane >> 2, tq = lane & 3;
    const int wm = (warp / WRN) * WM;
    const int wn = (warp % WRN) * WN;
    const int rowBase = blockIdx.y * BM;
    const int colBase = blockIdx.x * BN;
    const int kstart  = blockIdx.z * Kslice;
    const int KT = Kslice / 64;

    if (epi == EPI_NONE) Cf += (size_t)blockIdx.z * ((size_t)B_ * BN);

    const f16* Abh = Ah + (size_t)rowBase * Kd + kstart;
    const f16* Bbh = Bh + (size_t)colBase * Kd + kstart;

    // per-lane ldmatrix offsets: swizzled addr = row*128 + (kb ^ ((row&7)<<4))
    const int lr = lane & 15, lh = (lane >> 4) * 16;
    int aoff[MF], axr[MF], boff[NB], bxr[NB];
    #pragma unroll
    for (int fm = 0; fm < MF; ++fm) {
        int r = wm + fm * 16 + lr;
        aoff[fm] = r * 128; axr[fm] = (r & 7) << 4;
    }
    #pragma unroll
    for (int nb = 0; nb < NB; ++nb) {
        int r = wn + nb * 16 + lr;
        boff[nb] = r * 128; bxr[nb] = (r & 7) << 4;
    }

    float acc[MF][NF][4];
    #pragma unroll
    for (int i = 0; i < MF; ++i)
        #pragma unroll
        for (int j = 0; j < NF; ++j)
            #pragma unroll
            for (int c = 0; c < 4; ++c) acc[i][j][c] = 0.f;

    // ---- 2-stage cp.async pipeline ----
    #define STAGE_ALL(kt, buf) do {                                            \
        uint32_t d0 = sb + (buf) * STAGE;                                      \
        stage_cp<ABYTES, NT>(d0,          Abh + (kt) * 64, Kd);                \
        stage_cp<BBYTES, NT>(d0 + ABYTES, Bbh + (kt) * 64, Kd);                \
    } while (0)

    STAGE_ALL(0, 0);
    asm volatile("cp.async.commit_group;" ::: "memory");

    for (int kt = 0; kt < KT; ++kt) {
        if (kt + 1 < KT) {
            STAGE_ALL(kt + 1, (kt + 1) & 1);
            asm volatile("cp.async.commit_group;" ::: "memory");
            asm volatile("cp.async.wait_group 1;" ::: "memory");
        } else {
            asm volatile("cp.async.wait_group 0;" ::: "memory");
        }
        __syncthreads();

        const uint32_t base = sb + (kt & 1) * STAGE;
        const uint32_t Ahb = base;
        const uint32_t Bhb = base + ABYTES;

        #pragma unroll
        for (int ks = 0; ks < 4; ++ks) {
            const int kb = ks * 32 + lh;
            uint32_t ah[MF][4];
            #pragma unroll
            for (int fm = 0; fm < MF; ++fm)
                LDSM4(ah[fm], Ahb + aoff[fm] + (kb ^ axr[fm]));
            #pragma unroll
            for (int nb = 0; nb < NB; ++nb) {
                uint32_t b4[4];
                LDSM4(b4, Bhb + boff[nb] + (kb ^ bxr[nb]));
                #pragma unroll
                for (int odd = 0; odd < 2; ++odd) {
                    const int fn = nb * 2 + odd;
                    uint32_t bb[2] = { b4[odd], b4[odd + 2] };
                    #pragma unroll
                    for (int fm = 0; fm < MF; ++fm)
                        MMA_F16(acc[fm][fn], ah[fm], bb);
                }
            }
        }
        __syncthreads();
    }

    // ---- epilogue (runtime-selected; cold path) ----
    #pragma unroll
    for (int fm = 0; fm < MF; ++fm) {
        #pragma unroll
        for (int half = 0; half < 2; ++half) {
            const int row = rowBase + wm + fm * 16 + gq + half * 8;
            float r0 = 0.f;
            if (epi == EPI_DIST) r0 = aux0[row];
            if (epi == EPI_SRELU_BIAS) r0 = aux0[row] * aScale;
            #pragma unroll
            for (int fn = 0; fn < NF; ++fn) {
                const int col = colBase + wn + fn * 8 + tq * 2;
                float v0 = acc[fm][fn][half * 2 + 0];
                float v1 = acc[fm][fn][half * 2 + 1];
                if (epi == EPI_DIST) {
                    v0 = sqrtf(fmaxf(r0 + aux1[col]     - 2.f * v0, 0.f));
                    v1 = sqrtf(fmaxf(r0 + aux1[col + 1] - 2.f * v1, 0.f));
                } else if (epi == EPI_RELU_BIAS) {
                    v0 = fmaxf(fmaf(v0, aScale, bias[col]), 0.f);
                    v1 = fmaxf(fmaf(v1, aScale, bias[col + 1]), 0.f);
                } else if (epi == EPI_SRELU_BIAS) {
                    v0 = fmaxf(fmaf(v0, r0, bias[col]), 0.f);
                    v1 = fmaxf(fmaf(v1, r0, bias[col + 1]), 0.f);
                } else if (epi == EPI_BIAS) {
                    v0 = fmaf(v0, aScale, bias[col]);
                    v1 = fmaf(v1, aScale, bias[col + 1]);
                }
                if (epi == EPI_RELU_BIAS || epi == EPI_SRELU_BIAS) {
                    *(uint32_t*)&Ch[(size_t)row * N + col] =
                        pack2h(__float2half(v0 * outScale), __float2half(v1 * outScale));
                } else {
                    float2 o; o.x = v0; o.y = v1;
                    *(float2*)&Cf[(size_t)row * N + col] = o;
                }
            }
        }
    }
}

// ---------------- pre/post kernels ----------------
__global__ void sqnorm_kernel(const float* __restrict__ m, float* __restrict__ out, int rows) {
    int warp = (blockIdx.x * blockDim.x + threadIdx.x) >> 5;
    int lane = threadIdx.x & 31;
    if (warp >= rows) return;
    const float* r = m + (size_t)warp * D_;
    float s = 0.f;
    #pragma unroll
    for (int i = lane; i < D_; i += 32) { float v = r[i]; s += v * v; }
    #pragma unroll
    for (int o = 16; o; o >>= 1) s += __shfl_xor_sync(0xffffffffu, s, o);
    if (lane == 0) out[warp] = s;
}

// fp32 -> fp16 single, vectorized
__global__ void conv_kernel(const float* __restrict__ in, f16* __restrict__ o, int n4) {
    int i = blockIdx.x * blockDim.x + threadIdx.x;
    if (i >= n4) return;
    float4 v = ((const float4*)in)[i];
    ((uint2*)o)[i] = make_uint2(pack2h(__float2half(v.x), __float2half(v.y)),
                                pack2h(__float2half(v.z), __float2half(v.w)));
}

// in [R,C] fp32 row-major -> out [C,R] fp16 single
__global__ void transpose_h(const float* __restrict__ in, f16* __restrict__ o, int R, int C) {
    __shared__ float t[32][33];
    int cb = blockIdx.x * 32, rb = blockIdx.y * 32;
    int tx = threadIdx.x, ty = threadIdx.y;
    #pragma unroll
    for (int i = 0; i < 32; i += 8)
        t[ty + i][tx] = in[(size_t)(rb + ty + i) * C + cb + tx];
    __syncthreads();
    #pragma unroll
    for (int i = 0; i < 32; i += 8)
        o[(size_t)(cb + ty + i) * R + rb + tx] = __float2half(t[tx][ty + i]);
}

// score: p = exp(-10*diff/rowmax); store (p*SP_) f16 + rsc = 1/sum(p)
__global__ void __launch_bounds__(256) score_kernel(const float* __restrict__ s,
                                                    f16* __restrict__ ph,
                                                    float* __restrict__ rsc) {
    const int row = blockIdx.x;
    const float* p = s + (size_t)row * K_;
    const int tid = threadIdx.x;
    constexpr int PT = K_ / 256;
    float v[PT];
    float mx = 0.f;
    #pragma unroll
    for (int i = 0; i < PT; ++i) { v[i] = p[tid + i * 256]; mx = fmaxf(mx, v[i]); }
    __shared__ float red[256];
    red[tid] = mx; __syncthreads();
    #pragma unroll
    for (int o = 128; o; o >>= 1) { if (tid < o) red[tid] = fmaxf(red[tid], red[tid + o]); __syncthreads(); }
    mx = red[0];
    __syncthreads();
    const float scale = -10.f / mx;
    float sum = 0.f;
    #pragma unroll
    for (int i = 0; i < PT; ++i) { v[i] = __expf(v[i] * scale); sum += v[i]; }
    red[tid] = sum; __syncthreads();
    #pragma unroll
    for (int o = 128; o; o >>= 1) { if (tid < o) red[tid] += red[tid + o]; __syncthreads(); }
    #pragma unroll
    for (int i = 0; i < PT; ++i)
        ph[(size_t)row * K_ + tid + i * 256] = __float2half(v[i] * SP_);
    if (tid == 0) rsc[row] = 1.f / red[0];
}

// softmax: p = exp(l - rowmax); store (p*SP2_) f16 + rsc = 1/sum(p)
__global__ void __launch_bounds__(256) softmax_kernel(const float* __restrict__ s,
                                                      f16* __restrict__ ph,
                                                      float* __restrict__ rsc) {
    const int row = blockIdx.x;
    const float* p = s + (size_t)row * K_;
    const int tid = threadIdx.x;
    constexpr int PT = K_ / 256;
    float v[PT];
    float mx = -3.402823466e38f;
    #pragma unroll
    for (int i = 0; i < PT; ++i) { v[i] = p[tid + i * 256]; mx = fmaxf(mx, v[i]); }
    __shared__ float red[256];
    red[tid] = mx; __syncthreads();
    #pragma unroll
    for (int o = 128; o; o >>= 1) { if (tid < o) red[tid] = fmaxf(red[tid], red[tid + o]); __syncthreads(); }
    mx = red[0];
    __syncthreads();
    float sum = 0.f;
    #pragma unroll
    for (int i = 0; i < PT; ++i) { v[i] = __expf(v[i] - mx); sum += v[i]; }
    red[tid] = sum; __syncthreads();
    #pragma unroll
    for (int o = 128; o; o >>= 1) { if (tid < o) red[tid] += red[tid + o]; __syncthreads(); }
    #pragma unroll
    for (int i = 0; i < PT; ++i)
        ph[(size_t)row * K_ + tid + i * 256] = __float2half(v[i] * SP2_);
    if (tid == 0) rsc[row] = 1.f / red[0];
}

// out[b][v] = (rsc[b]/SP2_) * sum_j part[j][b][v]
__global__ void reduce_out(const float* __restrict__ part, const float* __restrict__ rsc,
                           float* __restrict__ out) {
    int i = blockIdx.x * blockDim.x + threadIdx.x;
    constexpr int BV = B_ * V_;
    if (i >= BV) return;
    float v = part[i] + part[i + BV] + part[i + 2 * BV] + part[i + 3 * BV];
    out[i] = v * rsc[i / V_] * (1.0f / SP2_);
}

// ---------------- launch ----------------
extern "C" void kernel_launch(void* const* d_in, const int* in_sizes, int n_in,
                              void* d_out, int out_size) {
    const float* x        = (const float*)d_in[0];
    const float* keys     = (const float*)d_in[1];
    const float* values   = (const float*)d_in[2];
    const float* W_embed  = (const float*)d_in[3];
    const float* b_embed  = (const float*)d_in[4];
    const float* W_hidden = (const float*)d_in[5];
    const float* b_hidden = (const float*)d_in[6];
    const float* W_att    = (const float*)d_in[7];
    const float* b_att    = (const float*)d_in[8];
    float* out = (float*)d_out;

    float *s, *x2, *k2, *rsc, *part;
    f16 *pc, *ec, *hc, *we, *wh, *wa, *vt, *xc, *kc;
    cudaGetSymbolAddress((void**)&s, g_s);
    cudaGetSymbolAddress((void**)&pc, g_p);
    cudaGetSymbolAddress((void**)&ec, g_e);
    cudaGetSymbolAddress((void**)&hc, g_h);
    cudaGetSymbolAddress((void**)&we, g_we);
    cudaGetSymbolAddress((void**)&wh, g_wh);
    cudaGetSymbolAddress((void**)&wa, g_wa);
    cudaGetSymbolAddress((void**)&vt, g_vt);
    cudaGetSymbolAddress((void**)&xc, g_xc);
    cudaGetSymbolAddress((void**)&kc, g_kc);
    cudaGetSymbolAddress((void**)&part, g_part);
    cudaGetSymbolAddress((void**)&x2, g_x2);
    cudaGetSymbolAddress((void**)&k2, g_k2);
    cudaGetSymbolAddress((void**)&rsc, g_rsc);

    // smem: 2 stages x (BM + BN)*128 bytes
    constexpr int SMEM_BIG = 2 * ((256 + 128) * 128);   // 98304
    constexpr int SMEM_SML = 2 * ((128 + 64) * 128);    // 49152
    cudaFuncSetAttribute((const void*)tc_gemm<256, 128, 4, 2>, cudaFuncAttributeMaxDynamicSharedMemorySize, SMEM_BIG);
    cudaFuncSetAttribute((const void*)tc_gemm<128, 64, 4, 2>,  cudaFuncAttributeMaxDynamicSharedMemorySize, SMEM_SML);

    // 0. preprocessing: norms, converts, weight transposes
    sqnorm_kernel<<<B_ / 8, 256>>>(x, x2, B_);
    sqnorm_kernel<<<K_ / 8, 256>>>(keys, k2, K_);
    conv_kernel<<<(B_ * D_ / 4 + 255) / 256, 256>>>(x, xc, B_ * D_ / 4);
    conv_kernel<<<(K_ * D_ / 4 + 255) / 256, 256>>>(keys, kc, K_ * D_ / 4);
    {
        dim3 blk(32, 8);
        transpose_h<<<dim3(E_ / 32, K_ / 32), blk>>>(W_embed, we, K_, E_);
        transpose_h<<<dim3(H_ / 32, E_ / 32), blk>>>(W_hidden, wh, E_, H_);
        transpose_h<<<dim3(K_ / 32, H_ / 32), blk>>>(W_att, wa, H_, K_);
        transpose_h<<<dim3(V_ / 32, K_ / 32), blk>>>(values, vt, K_, V_);
    }

    // 1. diff -> g_s (fp32)
    tc_gemm<256, 128, 4, 2><<<dim3(K_ / 128, B_ / 256, 1), 256, SMEM_BIG>>>(
        xc, kc, s, nullptr, K_, D_, D_, EPI_DIST, 1.f, 1.f, x2, k2, nullptr);

    // 2. score p (xSP_) + 1/sum
    score_kernel<<<B_, 256>>>(s, pc, rsc);

    // 3. e = relu(p @ We * rsc + b_embed); stored xSE_
    tc_gemm<256, 128, 4, 2><<<dim3(E_ / 128, B_ / 256, 1), 256, SMEM_BIG>>>(
        pc, we, nullptr, ec, E_, K_, K_, EPI_SRELU_BIAS, 1.f / SP_, SE_, rsc, nullptr, b_embed);

    // 4. h = relu(e @ Wh + b_hidden); acc scaled by 1/SE_, stored xSH_
    tc_gemm<256, 128, 4, 2><<<dim3(H_ / 128, B_ / 256, 1), 256, SMEM_BIG>>>(
        ec, wh, nullptr, hc, H_, E_, E_, EPI_RELU_BIAS, 1.f / SE_, SH_, nullptr, nullptr, b_hidden);

    // 5. logits = h @ Wa / SH_ + b_att -> g_s (fp32)
    tc_gemm<256, 128, 4, 2><<<dim3(K_ / 128, B_ / 256, 1), 256, SMEM_BIG>>>(
        hc, wa, s, nullptr, K_, H_, H_, EPI_BIAS, 1.f / SH_, 1.f, nullptr, nullptr, b_att);

    // 6. softmax p (xSP2_) + 1/sum
    softmax_kernel<<<B_, 256>>>(s, pc, rsc);

    // 7. out partials (split-K x4), then reduce * rsc / SP2_
    tc_gemm<128, 64, 4, 2><<<dim3(1, B_ / 128, 4), 256, SMEM_SML>>>(
        pc, vt, part, nullptr, V_, K_, K_ / 4, EPI_NONE, 1.f, 1.f, nullptr, nullptr, nullptr);
    reduce_out<<<(B_ * V_ + 255) / 256, 256>>>(part, rsc, out);
}